// round 6
// baseline (speedup 1.0000x reference)
#include <cuda_runtime.h>
#include <cuda_bf16.h>
#include <math_constants.h>
#include <cstdint>

// Problem constants
#define N_NODES 20000
#define N_PAD   20096          // 157 * 128
#define IN_CH   512
#define HC      512
#define HEADS   8
#define CH      64
#define E_EDGES 320000
#define E_LABEL 100000
#define BN_BLOCKS 128

// ---------------- scratch ----------------
__device__ __nv_bfloat16 g_xhi[N_PAD * IN_CH];
__device__ __nv_bfloat16 g_xlo[N_PAD * IN_CH];
__device__ __nv_bfloat16 g_wthi[2][IN_CH * HC];
__device__ __nv_bfloat16 g_wtlo[2][IN_CH * HC];
__device__ float g_xl[N_PAD * HC];
__device__ float g_xr[N_PAD * HC];
__device__ float g_out[N_NODES * HC];
__device__ int   g_deg[N_NODES + 1];
__device__ int   g_off[N_NODES + 1];
__device__ int   g_cur[N_NODES];
__device__ int   g_csr_src[E_EDGES];
__device__ int   g_bsum[32];
__device__ float g_psum[BN_BLOCKS * HC];
__device__ float g_psq [BN_BLOCKS * HC];
__device__ float g_scale[HC];
__device__ float g_shift[HC];

// ---------------- helpers ----------------
__device__ __forceinline__ uint32_t smem_u32(const void* p) {
    uint32_t a;
    asm("{ .reg .u64 t; cvta.to.shared.u64 t, %1; cvt.u32.u64 %0, t; }" : "=r"(a) : "l"(p));
    return a;
}
__device__ __forceinline__ void cp_async16(uint32_t sa, const void* ga) {
    asm volatile("cp.async.cg.shared.global [%0], [%1], 16;" :: "r"(sa), "l"(ga) : "memory");
}
__device__ __forceinline__ void cp_commit() {
    asm volatile("cp.async.commit_group;" ::: "memory");
}
__device__ __forceinline__ void cp_wait1() {
    asm volatile("cp.async.wait_group 1;" ::: "memory");
}
__device__ __forceinline__ void cp_wait0() {
    asm volatile("cp.async.wait_group 0;" ::: "memory");
}
__device__ __forceinline__ void ldm_x4(uint32_t* r, uint32_t addr) {
    asm volatile("ldmatrix.sync.aligned.m8n8.x4.shared.b16 {%0,%1,%2,%3}, [%4];"
                 : "=r"(r[0]), "=r"(r[1]), "=r"(r[2]), "=r"(r[3]) : "r"(addr));
}
__device__ __forceinline__ void mma16816(float* d, const uint32_t* a, const uint32_t* b) {
    asm volatile("mma.sync.aligned.m16n8k16.row.col.f32.bf16.bf16.f32 "
                 "{%0,%1,%2,%3}, {%4,%5,%6,%7}, {%8,%9}, {%0,%1,%2,%3};"
                 : "+f"(d[0]), "+f"(d[1]), "+f"(d[2]), "+f"(d[3])
                 : "r"(a[0]), "r"(a[1]), "r"(a[2]), "r"(a[3]), "r"(b[0]), "r"(b[1]));
}

// ---------------- fused conversion: x hi/lo split + W transpose/split + g_deg zero ----------------
#define CONVX_BLOCKS (N_PAD * IN_CH / 4 / 256)      // 10048
#define CONVW_BLOCKS (2 * IN_CH * HC / 256)         // 2048

__global__ void conv_fused_kernel(const float* __restrict__ x,
                                  const float* __restrict__ Wl,
                                  const float* __restrict__ Wr)
{
    int bid = blockIdx.x;
    if (bid < CONVX_BLOCKS) {
        int i4 = bid * 256 + threadIdx.x;
        if (i4 <= N_NODES) g_deg[i4] = 0;
        int i = i4 * 4;
        int row = i >> 9;
        float4 v = (row < N_NODES) ? *(const float4*)(x + i) : make_float4(0.f, 0.f, 0.f, 0.f);
        float a[4] = {v.x, v.y, v.z, v.w};
        __nv_bfloat16 h0 = __float2bfloat16(a[0]);
        __nv_bfloat16 h1 = __float2bfloat16(a[1]);
        __nv_bfloat16 h2 = __float2bfloat16(a[2]);
        __nv_bfloat16 h3 = __float2bfloat16(a[3]);
        __nv_bfloat16 l0 = __float2bfloat16(a[0] - __bfloat162float(h0));
        __nv_bfloat16 l1 = __float2bfloat16(a[1] - __bfloat162float(h1));
        __nv_bfloat16 l2 = __float2bfloat16(a[2] - __bfloat162float(h2));
        __nv_bfloat16 l3 = __float2bfloat16(a[3] - __bfloat162float(h3));
        uint32_t hi01 = ((uint32_t)__bfloat16_as_ushort(h1) << 16) | __bfloat16_as_ushort(h0);
        uint32_t hi23 = ((uint32_t)__bfloat16_as_ushort(h3) << 16) | __bfloat16_as_ushort(h2);
        uint32_t lo01 = ((uint32_t)__bfloat16_as_ushort(l1) << 16) | __bfloat16_as_ushort(l0);
        uint32_t lo23 = ((uint32_t)__bfloat16_as_ushort(l3) << 16) | __bfloat16_as_ushort(l2);
        *(uint2*)((char*)g_xhi + i * 2) = make_uint2(hi01, hi23);
        *(uint2*)((char*)g_xlo + i * 2) = make_uint2(lo01, lo23);
    } else {
        int j = (bid - CONVX_BLOCKS) * 256 + threadIdx.x;   // 0 .. 2*512*512-1
        int mat = j >> 18;
        int i = j & 0x3FFFF;                                // n*512 + k
        const float* W = mat ? Wr : Wl;
        int n = i >> 9, k = i & 511;
        float v = W[k * HC + n];
        __nv_bfloat16 h = __float2bfloat16(v);
        g_wthi[mat][i] = h;
        g_wtlo[mat][i] = __float2bfloat16(v - __bfloat162float(h));
    }
}

// ---------------- HMMA split-bf16 GEMM ----------------
// CTA tile 128x128, 4 warps each 64x64; 16 k-chunks of 32; per chunk do 3 combos.
#define SMS 80                      // smem row stride bytes (64B row + 16B pad)
#define TILE_BYTES (128 * SMS)      // 10240
#define STAGE_BYTES (4 * TILE_BYTES)
#define GSMEM_TOTAL (2 * STAGE_BYTES)   // 81920

__global__ void __launch_bounds__(128, 2) gemm_tc_kernel()
{
    extern __shared__ __align__(16) char smem[];

    const int tid  = threadIdx.x;
    const int wid  = tid >> 5;
    const int lane = tid & 31;
    const int wm   = wid & 1;        // m half (64)
    const int wn   = wid >> 1;       // n half (64)

    const int m0  = blockIdx.y * 128;
    const int n0  = blockIdx.x * 128;
    const int mat = blockIdx.z;

    const __nv_bfloat16* Ah = g_xhi + (size_t)m0 * IN_CH;
    const __nv_bfloat16* Al = g_xlo + (size_t)m0 * IN_CH;
    const __nv_bfloat16* Bh = g_wthi[mat] + (size_t)n0 * IN_CH;
    const __nv_bfloat16* Bl = g_wtlo[mat] + (size_t)n0 * IN_CH;
    float* C = mat ? g_xr : g_xl;

    const uint32_t sb = smem_u32(smem);
    const int r0 = tid >> 2;          // 0..31
    const int c0 = tid & 3;           // 16B chunk

    float acc[4][8][4];
#pragma unroll
    for (int i = 0; i < 4; i++)
#pragma unroll
        for (int j = 0; j < 8; j++)
#pragma unroll
            for (int q = 0; q < 4; q++) acc[i][j][q] = 0.f;

    auto issue = [&](int kc, int stg) {
        const uint32_t base = sb + stg * STAGE_BYTES;
        const int kel = kc * 32 + c0 * 8;
#pragma unroll
        for (int j = 0; j < 4; j++) {
            int row = r0 + j * 32;
            uint32_t so = row * SMS + c0 * 16;
            size_t  go = (size_t)row * IN_CH + kel;
            cp_async16(base + 0 * TILE_BYTES + so, Ah + go);
            cp_async16(base + 1 * TILE_BYTES + so, Al + go);
            cp_async16(base + 2 * TILE_BYTES + so, Bh + go);
            cp_async16(base + 3 * TILE_BYTES + so, Bl + go);
        }
    };

    issue(0, 0); cp_commit();

    for (int kc = 0; kc < 16; kc++) {
        if (kc + 1 < 16) { issue(kc + 1, (kc + 1) & 1); cp_commit(); cp_wait1(); }
        else             { cp_wait0(); }
        __syncthreads();

        const uint32_t base = sb + (kc & 1) * STAGE_BYTES;
#pragma unroll
        for (int ks = 0; ks < 2; ks++) {
            const int kb = ks * 32;
            uint32_t ah[4][4], al[4][4];
#pragma unroll
            for (int mt = 0; mt < 4; mt++) {
                int row = wm * 64 + mt * 16 + ((lane >> 3) & 1) * 8 + (lane & 7);
                uint32_t off = row * SMS + kb + ((lane >> 4) & 1) * 16;
                ldm_x4(ah[mt], base + 0 * TILE_BYTES + off);
                ldm_x4(al[mt], base + 1 * TILE_BYTES + off);
            }
            uint32_t bh[8][2], bl[8][2];
#pragma unroll
            for (int nh = 0; nh < 4; nh++) {
                int row = wn * 64 + nh * 16 + (lane >> 4) * 8 + (lane & 7);
                uint32_t off = row * SMS + kb + ((lane >> 3) & 1) * 16;
                uint32_t t[4];
                ldm_x4(t, base + 2 * TILE_BYTES + off);
                bh[nh * 2 + 0][0] = t[0]; bh[nh * 2 + 0][1] = t[1];
                bh[nh * 2 + 1][0] = t[2]; bh[nh * 2 + 1][1] = t[3];
                ldm_x4(t, base + 3 * TILE_BYTES + off);
                bl[nh * 2 + 0][0] = t[0]; bl[nh * 2 + 0][1] = t[1];
                bl[nh * 2 + 1][0] = t[2]; bl[nh * 2 + 1][1] = t[3];
            }
#pragma unroll
            for (int mt = 0; mt < 4; mt++)
#pragma unroll
                for (int nt = 0; nt < 8; nt++) {
                    mma16816(acc[mt][nt], ah[mt], bh[nt]);
                    mma16816(acc[mt][nt], ah[mt], bl[nt]);
                    mma16816(acc[mt][nt], al[mt], bh[nt]);
                }
        }
        __syncthreads();
    }

    const int g = lane >> 2;
    const int q = lane & 3;
#pragma unroll
    for (int mt = 0; mt < 4; mt++) {
#pragma unroll
        for (int nt = 0; nt < 8; nt++) {
            int row = m0 + wm * 64 + mt * 16 + g;
            int col = n0 + wn * 64 + nt * 8 + q * 2;
            *(float2*)&C[(size_t)row * HC + col] =
                make_float2(acc[mt][nt][0], acc[mt][nt][1]);
            *(float2*)&C[(size_t)(row + 8) * HC + col] =
                make_float2(acc[mt][nt][2], acc[mt][nt][3]);
        }
    }
}

// ---------------- CSR build ----------------
__global__ void hist_kernel(const int* __restrict__ ei)
{
    int e = blockIdx.x * blockDim.x + threadIdx.x;
    if (e < E_EDGES) atomicAdd(&g_deg[ei[E_EDGES + e]], 1);
}

__global__ void scan_blocks_kernel()     // 20 blocks x 1024
{
    __shared__ int wsum[32];
    int b = blockIdx.x, t = threadIdx.x;
    int i = b * 1024 + t;
    int v = (i < N_NODES) ? g_deg[i] : 0;
    int lane = t & 31, w = t >> 5;
    int s = v;
#pragma unroll
    for (int o = 1; o < 32; o <<= 1) {
        int u = __shfl_up_sync(0xffffffffu, s, o);
        if (lane >= o) s += u;
    }
    if (lane == 31) wsum[w] = s;
    __syncthreads();
    if (w == 0) {
        int ws = wsum[lane];
#pragma unroll
        for (int o = 1; o < 32; o <<= 1) {
            int u = __shfl_up_sync(0xffffffffu, ws, o);
            if (lane >= o) ws += u;
        }
        wsum[lane] = ws;
    }
    __syncthreads();
    int excl = s - v + (w > 0 ? wsum[w - 1] : 0);
    if (i < N_NODES) g_off[i] = excl;
    if (t == 1023) g_bsum[b] = excl + v;
}

__global__ void scan_add_kernel()        // 20 blocks x 1024
{
    __shared__ int boff;
    int b = blockIdx.x, t = threadIdx.x;
    if (t == 0) {
        int s = 0;
        for (int j = 0; j < b; j++) s += g_bsum[j];
        boff = s;
    }
    __syncthreads();
    int i = b * 1024 + t;
    if (i < N_NODES) {
        int o = g_off[i] + boff;
        g_off[i] = o;
        g_cur[i] = o;
    }
    if (i == 0) g_off[N_NODES] = E_EDGES;
}

__global__ void scatter_kernel(const int* __restrict__ ei)
{
    int e = blockIdx.x * blockDim.x + threadIdx.x;
    if (e < E_EDGES) {
        int d = ei[E_EDGES + e];
        int pos = atomicAdd(&g_cur[d], 1);
        g_csr_src[pos] = ei[e];
    }
}

// ---------------- GATv2 attention + aggregation (prefetch pipeline) ----------------
__global__ void attn_kernel(const float* __restrict__ att, const float* __restrict__ bias)
{
    int warp = (blockIdx.x * blockDim.x + threadIdx.x) >> 5;
    int lane = threadIdx.x & 31;
    if (warp >= N_NODES) return;
    const int dst = warp;
    const int c0  = lane * 16;

    float xr_[16], at_[16];
    {
        const float4* p = (const float4*)&g_xr[dst * HC + c0];
        const float4* q = (const float4*)&att[c0];
#pragma unroll
        for (int k = 0; k < 4; k++) {
            float4 a = p[k]; float4 b = q[k];
            xr_[4*k+0] = a.x; xr_[4*k+1] = a.y; xr_[4*k+2] = a.z; xr_[4*k+3] = a.w;
            at_[4*k+0] = b.x; at_[4*k+1] = b.y; at_[4*k+2] = b.z; at_[4*k+3] = b.w;
        }
    }

    float m = -CUDART_INF_F;
    float s = 0.f;
    float acc[16];
#pragma unroll
    for (int j = 0; j < 16; j++) acc[j] = 0.f;

    const int beg = g_off[dst], end = g_off[dst + 1];

    float xln[16];
    if (beg < end) {
        int src = g_csr_src[beg];
        const float4* q = (const float4*)&g_xl[src * HC + c0];
#pragma unroll
        for (int k = 0; k < 4; k++) {
            float4 a = q[k];
            xln[4*k+0] = a.x; xln[4*k+1] = a.y; xln[4*k+2] = a.z; xln[4*k+3] = a.w;
        }
    }

    for (int p = beg; p < end; p++) {
        float xl_[16];
#pragma unroll
        for (int j = 0; j < 16; j++) xl_[j] = xln[j];

        if (p + 1 < end) {                      // prefetch next edge's row
            int src = g_csr_src[p + 1];
            const float4* q = (const float4*)&g_xl[src * HC + c0];
#pragma unroll
            for (int k = 0; k < 4; k++) {
                float4 a = q[k];
                xln[4*k+0] = a.x; xln[4*k+1] = a.y; xln[4*k+2] = a.z; xln[4*k+3] = a.w;
            }
        }

        float part = 0.f;
#pragma unroll
        for (int j = 0; j < 16; j++) {
            float v = xl_[j] + xr_[j];
            float lr = (v > 0.f) ? v : 0.2f * v;
            part = fmaf(lr, at_[j], part);
        }
        part += __shfl_xor_sync(0xffffffffu, part, 1);
        part += __shfl_xor_sync(0xffffffffu, part, 2);

        float mnew = fmaxf(m, part);
        float corr = __expf(m - mnew);
        float w    = __expf(part - mnew);
        s = s * corr + w;
#pragma unroll
        for (int j = 0; j < 16; j++) acc[j] = fmaf(acc[j], corr, w * xl_[j]);
        m = mnew;
    }

    float inv = 1.f / (s + 1e-16f);
    const float4* bq = (const float4*)&bias[c0];
#pragma unroll
    for (int k = 0; k < 4; k++) {
        float4 b = bq[k];
        float4 o;
        o.x = fmaf(acc[4*k+0], inv, b.x);
        o.y = fmaf(acc[4*k+1], inv, b.y);
        o.z = fmaf(acc[4*k+2], inv, b.z);
        o.w = fmaf(acc[4*k+3], inv, b.w);
        *(float4*)&g_out[dst * HC + c0 + 4*k] = o;
    }
}

// ---------------- BatchNorm stats (deterministic 2-stage) ----------------
__global__ void bn_partial_kernel()
{
    int c = threadIdx.x;
    float s = 0.f, ss = 0.f;
    for (int r = blockIdx.x; r < N_NODES; r += gridDim.x) {
        float v = g_out[r * HC + c];
        s += v;
        ss = fmaf(v, v, ss);
    }
    g_psum[blockIdx.x * HC + c] = s;
    g_psq [blockIdx.x * HC + c] = ss;
}

__global__ void bn_final_kernel(const float* __restrict__ gamma, const float* __restrict__ beta)
{
    int c = threadIdx.x;
    float s = 0.f, ss = 0.f;
    for (int b = 0; b < BN_BLOCKS; b++) {
        s  += g_psum[b * HC + c];
        ss += g_psq [b * HC + c];
    }
    float mu  = s / (float)N_NODES;
    float var = ss / (float)N_NODES - mu * mu;
    float sc  = gamma[c] * rsqrtf(var + 1e-5f);
    g_scale[c] = sc;
    g_shift[c] = beta[c] - mu * sc;
}

// ---------------- link scoring with fused BN+ReLU ----------------
__global__ void link_kernel(const int* __restrict__ eli, float* __restrict__ out)
{
    int w = (blockIdx.x * blockDim.x + threadIdx.x) >> 5;
    int lane = threadIdx.x & 31;
    if (w >= E_LABEL) return;
    int a = eli[w];
    int b = eli[E_LABEL + w];
    const int c0 = lane * 16;
    const float4* pa = (const float4*)&g_out[a * HC + c0];
    const float4* pb = (const float4*)&g_out[b * HC + c0];
    const float4* psc = (const float4*)&g_scale[c0];
    const float4* psh = (const float4*)&g_shift[c0];
    float p = 0.f;
#pragma unroll
    for (int k = 0; k < 4; k++) {
        float4 va = pa[k], vb = pb[k];
        float4 sc = psc[k], sh = psh[k];
        float ax = fmaxf(fmaf(va.x, sc.x, sh.x), 0.f);
        float ay = fmaxf(fmaf(va.y, sc.y, sh.y), 0.f);
        float az = fmaxf(fmaf(va.z, sc.z, sh.z), 0.f);
        float aw = fmaxf(fmaf(va.w, sc.w, sh.w), 0.f);
        float bx = fmaxf(fmaf(vb.x, sc.x, sh.x), 0.f);
        float by = fmaxf(fmaf(vb.y, sc.y, sh.y), 0.f);
        float bz = fmaxf(fmaf(vb.z, sc.z, sh.z), 0.f);
        float bw = fmaxf(fmaf(vb.w, sc.w, sh.w), 0.f);
        p = fmaf(ax, bx, p);
        p = fmaf(ay, by, p);
        p = fmaf(az, bz, p);
        p = fmaf(aw, bw, p);
    }
#pragma unroll
    for (int off = 16; off > 0; off >>= 1)
        p += __shfl_xor_sync(0xffffffffu, p, off);
    if (lane == 0) out[w] = p;
}

// ---------------- launch ----------------
extern "C" void kernel_launch(void* const* d_in, const int* in_sizes, int n_in,
                              void* d_out, int out_size)
{
    const float* x     = (const float*)d_in[0];
    const int*   ei    = (const int*)  d_in[1];
    const int*   eli   = (const int*)  d_in[2];
    const float* W_l   = (const float*)d_in[3];
    const float* W_r   = (const float*)d_in[4];
    const float* att   = (const float*)d_in[5];
    const float* bias  = (const float*)d_in[6];
    const float* gamma = (const float*)d_in[7];
    const float* beta  = (const float*)d_in[8];
    float* out = (float*)d_out;

    static bool s_init = false;
    if (!s_init) {
        cudaFuncSetAttribute(gemm_tc_kernel,
                             cudaFuncAttributeMaxDynamicSharedMemorySize, GSMEM_TOTAL);
        s_init = true;
    }

    // fused conversions (also zeroes g_deg)
    conv_fused_kernel<<<CONVX_BLOCKS + CONVW_BLOCKS, 256>>>(x, W_l, W_r);

    // CSR build
    hist_kernel<<<(E_EDGES + 255) / 256, 256>>>(ei);
    scan_blocks_kernel<<<20, 1024>>>();
    scan_add_kernel<<<20, 1024>>>();
    scatter_kernel<<<(E_EDGES + 255) / 256, 256>>>(ei);

    // HMMA split-bf16 GEMMs
    {
        dim3 g(HC / 128, N_PAD / 128, 2);
        gemm_tc_kernel<<<g, 128, GSMEM_TOTAL>>>();
    }

    // attention + aggregation
    attn_kernel<<<(N_NODES * 32) / 256, 256>>>(att, bias);

    // batch norm stats
    bn_partial_kernel<<<BN_BLOCKS, HC>>>();
    bn_final_kernel<<<1, HC>>>(gamma, beta);

    // link scoring with fused BN + ReLU
    link_kernel<<<(E_LABEL * 32) / 256, 256>>>(eli, out);
}

// round 7
// speedup vs baseline: 1.0641x; 1.0641x over previous
#include <cuda_runtime.h>
#include <cuda_bf16.h>
#include <math_constants.h>
#include <cstdint>

// Problem constants
#define N_NODES 20000
#define N_PAD   20096          // 157 * 128
#define IN_CH   512
#define HC      512
#define HEADS   8
#define CH      64
#define E_EDGES 320000
#define E_LABEL 100000
#define ATTN_BLOCKS 2500       // 20000 warps / 8 per block
#define BN1_BLOCKS 128

// ---------------- scratch ----------------
__device__ __nv_bfloat16 g_xhi[N_PAD * IN_CH];
__device__ __nv_bfloat16 g_xlo[N_PAD * IN_CH];
__device__ __nv_bfloat16 g_wthi[2][IN_CH * HC];
__device__ __nv_bfloat16 g_wtlo[2][IN_CH * HC];
__device__ float g_xl[N_PAD * HC];
__device__ float g_xr[N_PAD * HC];
__device__ float g_out[N_NODES * HC];
__device__ int   g_deg[N_NODES + 1];
__device__ int   g_off[N_NODES + 1];
__device__ int   g_cur[N_NODES];
__device__ int   g_csr_src[E_EDGES];
__device__ int   g_bsum[32];
__device__ float g_ps [ATTN_BLOCKS * HC];    // per-attn-block channel sums
__device__ float g_pq [ATTN_BLOCKS * HC];    // per-attn-block channel sumsq
__device__ float g_ps1[BN1_BLOCKS * HC];
__device__ float g_pq1[BN1_BLOCKS * HC];
__device__ float g_scale[HC];
__device__ float g_shift[HC];

// ---------------- helpers ----------------
__device__ __forceinline__ uint32_t smem_u32(const void* p) {
    uint32_t a;
    asm("{ .reg .u64 t; cvta.to.shared.u64 t, %1; cvt.u32.u64 %0, t; }" : "=r"(a) : "l"(p));
    return a;
}
__device__ __forceinline__ void cp_async16(uint32_t sa, const void* ga) {
    asm volatile("cp.async.cg.shared.global [%0], [%1], 16;" :: "r"(sa), "l"(ga) : "memory");
}
__device__ __forceinline__ void cp_commit() {
    asm volatile("cp.async.commit_group;" ::: "memory");
}
__device__ __forceinline__ void cp_wait1() {
    asm volatile("cp.async.wait_group 1;" ::: "memory");
}
__device__ __forceinline__ void cp_wait0() {
    asm volatile("cp.async.wait_group 0;" ::: "memory");
}
__device__ __forceinline__ void ldm_x4(uint32_t* r, uint32_t addr) {
    asm volatile("ldmatrix.sync.aligned.m8n8.x4.shared.b16 {%0,%1,%2,%3}, [%4];"
                 : "=r"(r[0]), "=r"(r[1]), "=r"(r[2]), "=r"(r[3]) : "r"(addr));
}
__device__ __forceinline__ void mma16816(float* d, const uint32_t* a, const uint32_t* b) {
    asm volatile("mma.sync.aligned.m16n8k16.row.col.f32.bf16.bf16.f32 "
                 "{%0,%1,%2,%3}, {%4,%5,%6,%7}, {%8,%9}, {%0,%1,%2,%3};"
                 : "+f"(d[0]), "+f"(d[1]), "+f"(d[2]), "+f"(d[3])
                 : "r"(a[0]), "r"(a[1]), "r"(a[2]), "r"(a[3]), "r"(b[0]), "r"(b[1]));
}

// ---------------- fused conversion: x hi/lo split + W transpose/split + g_deg zero ----------------
#define CONVX_BLOCKS (N_PAD * IN_CH / 4 / 256)      // 10048
#define CONVW_BLOCKS (2 * IN_CH * HC / 256)         // 2048

__global__ void conv_fused_kernel(const float* __restrict__ x,
                                  const float* __restrict__ Wl,
                                  const float* __restrict__ Wr)
{
    int bid = blockIdx.x;
    if (bid < CONVX_BLOCKS) {
        int i4 = bid * 256 + threadIdx.x;
        if (i4 <= N_NODES) g_deg[i4] = 0;
        int i = i4 * 4;
        int row = i >> 9;
        float4 v = (row < N_NODES) ? *(const float4*)(x + i) : make_float4(0.f, 0.f, 0.f, 0.f);
        float a[4] = {v.x, v.y, v.z, v.w};
        __nv_bfloat16 h0 = __float2bfloat16(a[0]);
        __nv_bfloat16 h1 = __float2bfloat16(a[1]);
        __nv_bfloat16 h2 = __float2bfloat16(a[2]);
        __nv_bfloat16 h3 = __float2bfloat16(a[3]);
        __nv_bfloat16 l0 = __float2bfloat16(a[0] - __bfloat162float(h0));
        __nv_bfloat16 l1 = __float2bfloat16(a[1] - __bfloat162float(h1));
        __nv_bfloat16 l2 = __float2bfloat16(a[2] - __bfloat162float(h2));
        __nv_bfloat16 l3 = __float2bfloat16(a[3] - __bfloat162float(h3));
        uint32_t hi01 = ((uint32_t)__bfloat16_as_ushort(h1) << 16) | __bfloat16_as_ushort(h0);
        uint32_t hi23 = ((uint32_t)__bfloat16_as_ushort(h3) << 16) | __bfloat16_as_ushort(h2);
        uint32_t lo01 = ((uint32_t)__bfloat16_as_ushort(l1) << 16) | __bfloat16_as_ushort(l0);
        uint32_t lo23 = ((uint32_t)__bfloat16_as_ushort(l3) << 16) | __bfloat16_as_ushort(l2);
        *(uint2*)((char*)g_xhi + i * 2) = make_uint2(hi01, hi23);
        *(uint2*)((char*)g_xlo + i * 2) = make_uint2(lo01, lo23);
    } else {
        int j = (bid - CONVX_BLOCKS) * 256 + threadIdx.x;   // 0 .. 2*512*512-1
        int mat = j >> 18;
        int i = j & 0x3FFFF;                                // n*512 + k
        const float* W = mat ? Wr : Wl;
        int n = i >> 9, k = i & 511;
        float v = W[k * HC + n];
        __nv_bfloat16 h = __float2bfloat16(v);
        g_wthi[mat][i] = h;
        g_wtlo[mat][i] = __float2bfloat16(v - __bfloat162float(h));
    }
}

// ---------------- HMMA split-bf16 GEMM (R5 proven config) ----------------
#define SMS 80                      // smem row stride bytes (64B row + 16B pad)
#define TILE_BYTES (128 * SMS)      // 10240
#define STAGE_BYTES (4 * TILE_BYTES)
#define GSMEM_TOTAL (2 * STAGE_BYTES)   // 81920

__global__ void __launch_bounds__(256, 2) gemm_tc_kernel()
{
    extern __shared__ __align__(16) char smem[];

    const int tid  = threadIdx.x;
    const int wid  = tid >> 5;
    const int lane = tid & 31;
    const int wm   = wid & 1;
    const int wn   = wid >> 1;

    const int m0  = blockIdx.y * 128;
    const int n0  = blockIdx.x * 128;
    const int mat = blockIdx.z;

    const __nv_bfloat16* Ah = g_xhi + (size_t)m0 * IN_CH;
    const __nv_bfloat16* Al = g_xlo + (size_t)m0 * IN_CH;
    const __nv_bfloat16* Bh = g_wthi[mat] + (size_t)n0 * IN_CH;
    const __nv_bfloat16* Bl = g_wtlo[mat] + (size_t)n0 * IN_CH;
    float* C = mat ? g_xr : g_xl;

    const uint32_t sb = smem_u32(smem);
    const int r0 = tid >> 2;          // 0..63
    const int c0 = tid & 3;           // 16B chunk

    float acc[4][4][4];
#pragma unroll
    for (int i = 0; i < 4; i++)
#pragma unroll
        for (int j = 0; j < 4; j++)
#pragma unroll
            for (int q = 0; q < 4; q++) acc[i][j][q] = 0.f;

    auto issue = [&](int kc, int stg) {
        const uint32_t base = sb + stg * STAGE_BYTES;
        const int kel = kc * 32 + c0 * 8;
#pragma unroll
        for (int j = 0; j < 2; j++) {
            int row = r0 + j * 64;
            uint32_t so = row * SMS + c0 * 16;
            size_t  go = (size_t)row * IN_CH + kel;
            cp_async16(base + 0 * TILE_BYTES + so, Ah + go);
            cp_async16(base + 1 * TILE_BYTES + so, Al + go);
            cp_async16(base + 2 * TILE_BYTES + so, Bh + go);
            cp_async16(base + 3 * TILE_BYTES + so, Bl + go);
        }
    };

    issue(0, 0); cp_commit();

    for (int kc = 0; kc < 16; kc++) {
        if (kc + 1 < 16) { issue(kc + 1, (kc + 1) & 1); cp_commit(); cp_wait1(); }
        else             { cp_wait0(); }
        __syncthreads();

        const uint32_t base = sb + (kc & 1) * STAGE_BYTES;
#pragma unroll
        for (int ks = 0; ks < 2; ks++) {
            const int kb = ks * 32;
            uint32_t ah[4][4], al[4][4];
#pragma unroll
            for (int mt = 0; mt < 4; mt++) {
                int row = wm * 64 + mt * 16 + ((lane >> 3) & 1) * 8 + (lane & 7);
                uint32_t off = row * SMS + kb + ((lane >> 4) & 1) * 16;
                ldm_x4(ah[mt], base + 0 * TILE_BYTES + off);
                ldm_x4(al[mt], base + 1 * TILE_BYTES + off);
            }
            uint32_t bh[4][2], bl[4][2];
#pragma unroll
            for (int nh = 0; nh < 2; nh++) {
                int row = wn * 32 + nh * 16 + (lane >> 4) * 8 + (lane & 7);
                uint32_t off = row * SMS + kb + ((lane >> 3) & 1) * 16;
                uint32_t t[4];
                ldm_x4(t, base + 2 * TILE_BYTES + off);
                bh[nh * 2 + 0][0] = t[0]; bh[nh * 2 + 0][1] = t[1];
                bh[nh * 2 + 1][0] = t[2]; bh[nh * 2 + 1][1] = t[3];
                ldm_x4(t, base + 3 * TILE_BYTES + off);
                bl[nh * 2 + 0][0] = t[0]; bl[nh * 2 + 0][1] = t[1];
                bl[nh * 2 + 1][0] = t[2]; bl[nh * 2 + 1][1] = t[3];
            }
#pragma unroll
            for (int mt = 0; mt < 4; mt++)
#pragma unroll
                for (int nt = 0; nt < 4; nt++) {
                    mma16816(acc[mt][nt], ah[mt], bh[nt]);
                    mma16816(acc[mt][nt], ah[mt], bl[nt]);
                    mma16816(acc[mt][nt], al[mt], bh[nt]);
                }
        }
        __syncthreads();
    }

    const int g = lane >> 2;
    const int q = lane & 3;
#pragma unroll
    for (int mt = 0; mt < 4; mt++) {
#pragma unroll
        for (int nt = 0; nt < 4; nt++) {
            int row = m0 + wm * 64 + mt * 16 + g;
            int col = n0 + wn * 32 + nt * 8 + q * 2;
            *(float2*)&C[(size_t)row * HC + col] =
                make_float2(acc[mt][nt][0], acc[mt][nt][1]);
            *(float2*)&C[(size_t)(row + 8) * HC + col] =
                make_float2(acc[mt][nt][2], acc[mt][nt][3]);
        }
    }
}

// ---------------- CSR build ----------------
__global__ void hist_kernel(const int* __restrict__ ei)
{
    int e = blockIdx.x * blockDim.x + threadIdx.x;
    if (e < E_EDGES) atomicAdd(&g_deg[ei[E_EDGES + e]], 1);
}

__global__ void scan_blocks_kernel()     // 20 blocks x 1024
{
    __shared__ int wsum[32];
    int b = blockIdx.x, t = threadIdx.x;
    int i = b * 1024 + t;
    int v = (i < N_NODES) ? g_deg[i] : 0;
    int lane = t & 31, w = t >> 5;
    int s = v;
#pragma unroll
    for (int o = 1; o < 32; o <<= 1) {
        int u = __shfl_up_sync(0xffffffffu, s, o);
        if (lane >= o) s += u;
    }
    if (lane == 31) wsum[w] = s;
    __syncthreads();
    if (w == 0) {
        int ws = wsum[lane];
#pragma unroll
        for (int o = 1; o < 32; o <<= 1) {
            int u = __shfl_up_sync(0xffffffffu, ws, o);
            if (lane >= o) ws += u;
        }
        wsum[lane] = ws;
    }
    __syncthreads();
    int excl = s - v + (w > 0 ? wsum[w - 1] : 0);
    if (i < N_NODES) g_off[i] = excl;
    if (t == 1023) g_bsum[b] = excl + v;
}

__global__ void scan_add_kernel()        // 20 blocks x 1024
{
    __shared__ int boff;
    int b = blockIdx.x, t = threadIdx.x;
    if (t == 0) {
        int s = 0;
        for (int j = 0; j < b; j++) s += g_bsum[j];
        boff = s;
    }
    __syncthreads();
    int i = b * 1024 + t;
    if (i < N_NODES) {
        int o = g_off[i] + boff;
        g_off[i] = o;
        g_cur[i] = o;
    }
    if (i == 0) g_off[N_NODES] = E_EDGES;
}

__global__ void scatter_kernel(const int* __restrict__ ei)
{
    int e = blockIdx.x * blockDim.x + threadIdx.x;
    if (e < E_EDGES) {
        int d = ei[E_EDGES + e];
        int pos = atomicAdd(&g_cur[d], 1);
        g_csr_src[pos] = ei[e];
    }
}

// ---------------- GATv2 attention + aggregation + fused BN partial sums ----------------
// grid = ATTN_BLOCKS (2500) x 256 threads; warp w handles node blockIdx*8+w (exact cover)
__global__ void attn_kernel(const float* __restrict__ att, const float* __restrict__ bias)
{
    __shared__ float sbuf[8][HC / 32 * 16];   // [warp][512/32*16]=[8][256]? -> use [8][512]
    // NOTE: each lane owns 16 contiguous channels: c0 = lane*16 -> 512 per warp
    __shared__ float srow[8][512];

    const int wid  = threadIdx.x >> 5;
    const int lane = threadIdx.x & 31;
    const int dst  = blockIdx.x * 8 + wid;
    const int c0   = lane * 16;

    float xr_[16], at_[16];
    {
        const float4* p = (const float4*)&g_xr[dst * HC + c0];
        const float4* q = (const float4*)&att[c0];
#pragma unroll
        for (int k = 0; k < 4; k++) {
            float4 a = p[k]; float4 b = q[k];
            xr_[4*k+0] = a.x; xr_[4*k+1] = a.y; xr_[4*k+2] = a.z; xr_[4*k+3] = a.w;
            at_[4*k+0] = b.x; at_[4*k+1] = b.y; at_[4*k+2] = b.z; at_[4*k+3] = b.w;
        }
    }

    float m = -CUDART_INF_F;
    float s = 0.f;
    float acc[16];
#pragma unroll
    for (int j = 0; j < 16; j++) acc[j] = 0.f;

    const int beg = g_off[dst], end = g_off[dst + 1];

    float xln[16];
    if (beg < end) {
        int src = g_csr_src[beg];
        const float4* q = (const float4*)&g_xl[src * HC + c0];
#pragma unroll
        for (int k = 0; k < 4; k++) {
            float4 a = q[k];
            xln[4*k+0] = a.x; xln[4*k+1] = a.y; xln[4*k+2] = a.z; xln[4*k+3] = a.w;
        }
    }

    for (int p = beg; p < end; p++) {
        float xl_[16];
#pragma unroll
        for (int j = 0; j < 16; j++) xl_[j] = xln[j];

        if (p + 1 < end) {
            int src = g_csr_src[p + 1];
            const float4* q = (const float4*)&g_xl[src * HC + c0];
#pragma unroll
            for (int k = 0; k < 4; k++) {
                float4 a = q[k];
                xln[4*k+0] = a.x; xln[4*k+1] = a.y; xln[4*k+2] = a.z; xln[4*k+3] = a.w;
            }
        }

        float part = 0.f;
#pragma unroll
        for (int j = 0; j < 16; j++) {
            float v = xl_[j] + xr_[j];
            float lr = (v > 0.f) ? v : 0.2f * v;
            part = fmaf(lr, at_[j], part);
        }
        part += __shfl_xor_sync(0xffffffffu, part, 1);
        part += __shfl_xor_sync(0xffffffffu, part, 2);

        float mnew = fmaxf(m, part);
        float corr = __expf(m - mnew);
        float w    = __expf(part - mnew);
        s = s * corr + w;
#pragma unroll
        for (int j = 0; j < 16; j++) acc[j] = fmaf(acc[j], corr, w * xl_[j]);
        m = mnew;
    }

    float inv = 1.f / (s + 1e-16f);
    const float4* bq = (const float4*)&bias[c0];
#pragma unroll
    for (int k = 0; k < 4; k++) {
        float4 b = bq[k];
        float4 o;
        o.x = fmaf(acc[4*k+0], inv, b.x);
        o.y = fmaf(acc[4*k+1], inv, b.y);
        o.z = fmaf(acc[4*k+2], inv, b.z);
        o.w = fmaf(acc[4*k+3], inv, b.w);
        *(float4*)&g_out[dst * HC + c0 + 4*k] = o;
        *(float4*)&srow[wid][c0 + 4*k] = o;
    }

    __syncthreads();
    // fixed-order per-block channel reduction: thread t handles channels t, t+256
    {
        int t = threadIdx.x;
#pragma unroll
        for (int h = 0; h < 2; h++) {
            int c = t + h * 256;
            float ps = 0.f, pq = 0.f;
#pragma unroll
            for (int w = 0; w < 8; w++) {
                float v = srow[w][c];
                ps += v;
                pq = fmaf(v, v, pq);
            }
            g_ps[blockIdx.x * HC + c] = ps;
            g_pq[blockIdx.x * HC + c] = pq;
        }
    }
    (void)sbuf;
}

// ---------------- BN reduction stages ----------------
__global__ void bn_stage1_kernel()      // 128 blocks x 512
{
    int c = threadIdx.x;
    float s = 0.f, ss = 0.f;
    for (int r = blockIdx.x; r < ATTN_BLOCKS; r += BN1_BLOCKS) {
        s  += g_ps[r * HC + c];
        ss += g_pq[r * HC + c];
    }
    g_ps1[blockIdx.x * HC + c] = s;
    g_pq1[blockIdx.x * HC + c] = ss;
}

__global__ void bn_final_kernel(const float* __restrict__ gamma, const float* __restrict__ beta)
{
    int c = threadIdx.x;
    float s = 0.f, ss = 0.f;
    for (int b = 0; b < BN1_BLOCKS; b++) {
        s  += g_ps1[b * HC + c];
        ss += g_pq1[b * HC + c];
    }
    float mu  = s / (float)N_NODES;
    float var = ss / (float)N_NODES - mu * mu;
    float sc  = gamma[c] * rsqrtf(var + 1e-5f);
    g_scale[c] = sc;
    g_shift[c] = beta[c] - mu * sc;
}

// ---------------- link scoring with fused BN+ReLU ----------------
__global__ void link_kernel(const int* __restrict__ eli, float* __restrict__ out)
{
    int w = (blockIdx.x * blockDim.x + threadIdx.x) >> 5;
    int lane = threadIdx.x & 31;
    if (w >= E_LABEL) return;
    int a = eli[w];
    int b = eli[E_LABEL + w];
    const int c0 = lane * 16;
    const float4* pa = (const float4*)&g_out[a * HC + c0];
    const float4* pb = (const float4*)&g_out[b * HC + c0];
    const float4* psc = (const float4*)&g_scale[c0];
    const float4* psh = (const float4*)&g_shift[c0];
    float p = 0.f;
#pragma unroll
    for (int k = 0; k < 4; k++) {
        float4 va = pa[k], vb = pb[k];
        float4 sc = psc[k], sh = psh[k];
        float ax = fmaxf(fmaf(va.x, sc.x, sh.x), 0.f);
        float ay = fmaxf(fmaf(va.y, sc.y, sh.y), 0.f);
        float az = fmaxf(fmaf(va.z, sc.z, sh.z), 0.f);
        float aw = fmaxf(fmaf(va.w, sc.w, sh.w), 0.f);
        float bx = fmaxf(fmaf(vb.x, sc.x, sh.x), 0.f);
        float by = fmaxf(fmaf(vb.y, sc.y, sh.y), 0.f);
        float bz = fmaxf(fmaf(vb.z, sc.z, sh.z), 0.f);
        float bw = fmaxf(fmaf(vb.w, sc.w, sh.w), 0.f);
        p = fmaf(ax, bx, p);
        p = fmaf(ay, by, p);
        p = fmaf(az, bz, p);
        p = fmaf(aw, bw, p);
    }
#pragma unroll
    for (int off = 16; off > 0; off >>= 1)
        p += __shfl_xor_sync(0xffffffffu, p, off);
    if (lane == 0) out[w] = p;
}

// ---------------- launch ----------------
extern "C" void kernel_launch(void* const* d_in, const int* in_sizes, int n_in,
                              void* d_out, int out_size)
{
    const float* x     = (const float*)d_in[0];
    const int*   ei    = (const int*)  d_in[1];
    const int*   eli   = (const int*)  d_in[2];
    const float* W_l   = (const float*)d_in[3];
    const float* W_r   = (const float*)d_in[4];
    const float* att   = (const float*)d_in[5];
    const float* bias  = (const float*)d_in[6];
    const float* gamma = (const float*)d_in[7];
    const float* beta  = (const float*)d_in[8];
    float* out = (float*)d_out;

    static bool s_init = false;
    if (!s_init) {
        cudaFuncSetAttribute(gemm_tc_kernel,
                             cudaFuncAttributeMaxDynamicSharedMemorySize, GSMEM_TOTAL);
        s_init = true;
    }

    // #1 fused conversions (also zeroes g_deg)
    conv_fused_kernel<<<CONVX_BLOCKS + CONVW_BLOCKS, 256>>>(x, W_l, W_r);

    // #2-#3 CSR build front half
    hist_kernel<<<(E_EDGES + 255) / 256, 256>>>(ei);
    scan_blocks_kernel<<<20, 1024>>>();

    // #4 HMMA split-bf16 GEMMs (positioned 4th so ncu captures it)
    {
        dim3 g(HC / 128, N_PAD / 128, 2);
        gemm_tc_kernel<<<g, 256, GSMEM_TOTAL>>>();
    }

    // #5-#6 CSR build back half
    scan_add_kernel<<<20, 1024>>>();
    scatter_kernel<<<(E_EDGES + 255) / 256, 256>>>(ei);

    // #7 attention + aggregation (+ BN partial sums)
    attn_kernel<<<ATTN_BLOCKS, 256>>>(att, bias);

    // #8-#9 BN reduction
    bn_stage1_kernel<<<BN1_BLOCKS, HC>>>();
    bn_final_kernel<<<1, HC>>>(gamma, beta);

    // #10 link scoring with fused BN + ReLU
    link_kernel<<<(E_LABEL * 32) / 256, 256>>>(eli, out);
}

// round 8
// speedup vs baseline: 1.1508x; 1.0815x over previous
#include <cuda_runtime.h>
#include <cuda_bf16.h>
#include <math_constants.h>
#include <cstdint>

// Problem constants
#define N_NODES 20000
#define N_PAD   20096          // 157 * 128
#define IN_CH   512
#define HC      512
#define HEADS   8
#define CH      64
#define E_EDGES 320000
#define E_LABEL 100000
#define ATTN_BLOCKS 5000       // 20000 nodes / 4 warps per block
#define BN1_BLOCKS 128

// ---------------- scratch ----------------
__device__ __nv_bfloat16 g_xhi[N_PAD * IN_CH];
__device__ __nv_bfloat16 g_xlo[N_PAD * IN_CH];
__device__ __nv_bfloat16 g_wthi[2][IN_CH * HC];
__device__ __nv_bfloat16 g_wtlo[2][IN_CH * HC];
__device__ float g_xl[N_PAD * HC];
__device__ float g_xr[N_PAD * HC];
__device__ float g_out[N_NODES * HC];
__device__ int   g_deg[N_NODES + 1];
__device__ int   g_off[N_NODES + 1];
__device__ int   g_cur[N_NODES];
__device__ int   g_csr_src[E_EDGES];
__device__ int   g_bsum[32];
__device__ float g_ps [ATTN_BLOCKS * HC];
__device__ float g_pq [ATTN_BLOCKS * HC];
__device__ float g_ps1[BN1_BLOCKS * HC];
__device__ float g_pq1[BN1_BLOCKS * HC];
__device__ float g_scale[HC];
__device__ float g_shift[HC];

// ---------------- helpers ----------------
__device__ __forceinline__ uint32_t smem_u32(const void* p) {
    uint32_t a;
    asm("{ .reg .u64 t; cvta.to.shared.u64 t, %1; cvt.u32.u64 %0, t; }" : "=r"(a) : "l"(p));
    return a;
}
__device__ __forceinline__ void cp_async16(uint32_t sa, const void* ga) {
    asm volatile("cp.async.cg.shared.global [%0], [%1], 16;" :: "r"(sa), "l"(ga) : "memory");
}
__device__ __forceinline__ void cp_commit() {
    asm volatile("cp.async.commit_group;" ::: "memory");
}
__device__ __forceinline__ void cp_wait0() {
    asm volatile("cp.async.wait_group 0;" ::: "memory");
}
__device__ __forceinline__ void ldm_x4(uint32_t* r, uint32_t addr) {
    asm volatile("ldmatrix.sync.aligned.m8n8.x4.shared.b16 {%0,%1,%2,%3}, [%4];"
                 : "=r"(r[0]), "=r"(r[1]), "=r"(r[2]), "=r"(r[3]) : "r"(addr));
}
__device__ __forceinline__ void mma16816(float* d, const uint32_t* a, const uint32_t* b) {
    asm volatile("mma.sync.aligned.m16n8k16.row.col.f32.bf16.bf16.f32 "
                 "{%0,%1,%2,%3}, {%4,%5,%6,%7}, {%8,%9}, {%0,%1,%2,%3};"
                 : "+f"(d[0]), "+f"(d[1]), "+f"(d[2]), "+f"(d[3])
                 : "r"(a[0]), "r"(a[1]), "r"(a[2]), "r"(a[3]), "r"(b[0]), "r"(b[1]));
}

// ---------------- fused conversion: x hi/lo split + W transpose/split + g_deg zero ----------------
#define CONVX_BLOCKS (N_PAD * IN_CH / 4 / 256)      // 10048
#define CONVW_BLOCKS (2 * IN_CH * HC / 256)         // 2048

__global__ void conv_fused_kernel(const float* __restrict__ x,
                                  const float* __restrict__ Wl,
                                  const float* __restrict__ Wr)
{
    int bid = blockIdx.x;
    if (bid < CONVX_BLOCKS) {
        int i4 = bid * 256 + threadIdx.x;
        if (i4 <= N_NODES) g_deg[i4] = 0;
        int i = i4 * 4;
        int row = i >> 9;
        float4 v = (row < N_NODES) ? *(const float4*)(x + i) : make_float4(0.f, 0.f, 0.f, 0.f);
        float a[4] = {v.x, v.y, v.z, v.w};
        __nv_bfloat16 h0 = __float2bfloat16(a[0]);
        __nv_bfloat16 h1 = __float2bfloat16(a[1]);
        __nv_bfloat16 h2 = __float2bfloat16(a[2]);
        __nv_bfloat16 h3 = __float2bfloat16(a[3]);
        __nv_bfloat16 l0 = __float2bfloat16(a[0] - __bfloat162float(h0));
        __nv_bfloat16 l1 = __float2bfloat16(a[1] - __bfloat162float(h1));
        __nv_bfloat16 l2 = __float2bfloat16(a[2] - __bfloat162float(h2));
        __nv_bfloat16 l3 = __float2bfloat16(a[3] - __bfloat162float(h3));
        uint32_t hi01 = ((uint32_t)__bfloat16_as_ushort(h1) << 16) | __bfloat16_as_ushort(h0);
        uint32_t hi23 = ((uint32_t)__bfloat16_as_ushort(h3) << 16) | __bfloat16_as_ushort(h2);
        uint32_t lo01 = ((uint32_t)__bfloat16_as_ushort(l1) << 16) | __bfloat16_as_ushort(l0);
        uint32_t lo23 = ((uint32_t)__bfloat16_as_ushort(l3) << 16) | __bfloat16_as_ushort(l2);
        *(uint2*)((char*)g_xhi + i * 2) = make_uint2(hi01, hi23);
        *(uint2*)((char*)g_xlo + i * 2) = make_uint2(lo01, lo23);
    } else {
        int j = (bid - CONVX_BLOCKS) * 256 + threadIdx.x;
        int mat = j >> 18;
        int i = j & 0x3FFFF;                                // n*512 + k
        const float* W = mat ? Wr : Wl;
        int n = i >> 9, k = i & 511;
        float v = W[k * HC + n];
        __nv_bfloat16 h = __float2bfloat16(v);
        g_wthi[mat][i] = h;
        g_wtlo[mat][i] = __float2bfloat16(v - __bfloat162float(h));
    }
}

// ---------------- HMMA split-bf16 GEMM ----------------
#define SMS 80                      // smem row stride bytes (64B row + 16B pad)
#define TILE_BYTES (128 * SMS)      // 10240
#define STAGE_BYTES (4 * TILE_BYTES)
#define GSMEM_TOTAL (2 * STAGE_BYTES)   // 81920

__global__ void __launch_bounds__(256, 2) gemm_tc_kernel()
{
    extern __shared__ __align__(16) char smem[];

    const int tid  = threadIdx.x;
    const int wid  = tid >> 5;
    const int lane = tid & 31;
    const int wm   = wid & 1;
    const int wn   = wid >> 1;

    const int m0  = blockIdx.y * 128;
    const int n0  = blockIdx.x * 128;
    const int mat = blockIdx.z;

    const __nv_bfloat16* Ah = g_xhi + (size_t)m0 * IN_CH;
    const __nv_bfloat16* Al = g_xlo + (size_t)m0 * IN_CH;
    const __nv_bfloat16* Bh = g_wthi[mat] + (size_t)n0 * IN_CH;
    const __nv_bfloat16* Bl = g_wtlo[mat] + (size_t)n0 * IN_CH;
    float* C = mat ? g_xr : g_xl;

    const uint32_t sb = smem_u32(smem);
    const int r0 = tid >> 2;          // 0..63
    const int c0 = tid & 3;           // 16B chunk

    float acc[4][4][4];
#pragma unroll
    for (int i = 0; i < 4; i++)
#pragma unroll
        for (int j = 0; j < 4; j++)
#pragma unroll
            for (int q = 0; q < 4; q++) acc[i][j][q] = 0.f;

    auto issue = [&](int kc, int stg) {
        const uint32_t base = sb + stg * STAGE_BYTES;
        const int kel = kc * 32 + c0 * 8;
#pragma unroll
        for (int j = 0; j < 2; j++) {
            int row = r0 + j * 64;
            uint32_t so = row * SMS + c0 * 16;
            size_t  go = (size_t)row * IN_CH + kel;
            cp_async16(base + 0 * TILE_BYTES + so, Ah + go);
            cp_async16(base + 1 * TILE_BYTES + so, Al + go);
            cp_async16(base + 2 * TILE_BYTES + so, Bh + go);
            cp_async16(base + 3 * TILE_BYTES + so, Bl + go);
        }
    };

    issue(0, 0); cp_commit();

    for (int kc = 0; kc < 16; kc++) {
        cp_wait0();                 // chunk kc arrived (issued last iteration)
        __syncthreads();            // all warps done computing chunk kc-1
        if (kc + 1 < 16) { issue(kc + 1, (kc + 1) & 1); cp_commit(); }

        const uint32_t base = sb + (kc & 1) * STAGE_BYTES;
#pragma unroll
        for (int ks = 0; ks < 2; ks++) {
            const int kb = ks * 32;
            // B fragments first
            uint32_t bh[4][2], bl[4][2];
#pragma unroll
            for (int nh = 0; nh < 2; nh++) {
                int row = wn * 32 + nh * 16 + (lane >> 4) * 8 + (lane & 7);
                uint32_t off = row * SMS + kb + ((lane >> 3) & 1) * 16;
                uint32_t t[4];
                ldm_x4(t, base + 2 * TILE_BYTES + off);
                bh[nh * 2 + 0][0] = t[0]; bh[nh * 2 + 0][1] = t[1];
                bh[nh * 2 + 1][0] = t[2]; bh[nh * 2 + 1][1] = t[3];
                ldm_x4(t, base + 3 * TILE_BYTES + off);
                bl[nh * 2 + 0][0] = t[0]; bl[nh * 2 + 0][1] = t[1];
                bl[nh * 2 + 1][0] = t[2]; bl[nh * 2 + 1][1] = t[3];
            }
            // A row 0, then interleave: prefetch row mt+1 while issuing row mt's MMAs
            uint32_t ah[4][4], al[4][4];
            {
                int row = wm * 64 + ((lane >> 3) & 1) * 8 + (lane & 7);
                uint32_t off = row * SMS + kb + ((lane >> 4) & 1) * 16;
                ldm_x4(ah[0], base + 0 * TILE_BYTES + off);
                ldm_x4(al[0], base + 1 * TILE_BYTES + off);
            }
#pragma unroll
            for (int mt = 0; mt < 4; mt++) {
                if (mt < 3) {
                    int row = wm * 64 + (mt + 1) * 16 + ((lane >> 3) & 1) * 8 + (lane & 7);
                    uint32_t off = row * SMS + kb + ((lane >> 4) & 1) * 16;
                    ldm_x4(ah[mt + 1], base + 0 * TILE_BYTES + off);
                    ldm_x4(al[mt + 1], base + 1 * TILE_BYTES + off);
                }
#pragma unroll
                for (int nt = 0; nt < 4; nt++) {
                    mma16816(acc[mt][nt], ah[mt], bh[nt]);
                    mma16816(acc[mt][nt], ah[mt], bl[nt]);
                    mma16816(acc[mt][nt], al[mt], bh[nt]);
                }
            }
        }
    }

    const int g = lane >> 2;
    const int q = lane & 3;
#pragma unroll
    for (int mt = 0; mt < 4; mt++) {
#pragma unroll
        for (int nt = 0; nt < 4; nt++) {
            int row = m0 + wm * 64 + mt * 16 + g;
            int col = n0 + wn * 32 + nt * 8 + q * 2;
            *(float2*)&C[(size_t)row * HC + col] =
                make_float2(acc[mt][nt][0], acc[mt][nt][1]);
            *(float2*)&C[(size_t)(row + 8) * HC + col] =
                make_float2(acc[mt][nt][2], acc[mt][nt][3]);
        }
    }
}

// ---------------- CSR build ----------------
__global__ void hist_kernel(const int* __restrict__ ei)
{
    int e = blockIdx.x * blockDim.x + threadIdx.x;
    if (e < E_EDGES) atomicAdd(&g_deg[ei[E_EDGES + e]], 1);
}

__global__ void scan_blocks_kernel()     // 20 blocks x 1024
{
    __shared__ int wsum[32];
    int b = blockIdx.x, t = threadIdx.x;
    int i = b * 1024 + t;
    int v = (i < N_NODES) ? g_deg[i] : 0;
    int lane = t & 31, w = t >> 5;
    int s = v;
#pragma unroll
    for (int o = 1; o < 32; o <<= 1) {
        int u = __shfl_up_sync(0xffffffffu, s, o);
        if (lane >= o) s += u;
    }
    if (lane == 31) wsum[w] = s;
    __syncthreads();
    if (w == 0) {
        int ws = wsum[lane];
#pragma unroll
        for (int o = 1; o < 32; o <<= 1) {
            int u = __shfl_up_sync(0xffffffffu, ws, o);
            if (lane >= o) ws += u;
        }
        wsum[lane] = ws;
    }
    __syncthreads();
    int excl = s - v + (w > 0 ? wsum[w - 1] : 0);
    if (i < N_NODES) g_off[i] = excl;
    if (t == 1023) g_bsum[b] = excl + v;
}

__global__ void scan_add_kernel()        // 20 blocks x 1024
{
    __shared__ int boff;
    int b = blockIdx.x, t = threadIdx.x;
    if (t == 0) {
        int s = 0;
        for (int j = 0; j < b; j++) s += g_bsum[j];
        boff = s;
    }
    __syncthreads();
    int i = b * 1024 + t;
    if (i < N_NODES) {
        int o = g_off[i] + boff;
        g_off[i] = o;
        g_cur[i] = o;
    }
    if (i == 0) g_off[N_NODES] = E_EDGES;
}

__global__ void scatter_kernel(const int* __restrict__ ei)
{
    int e = blockIdx.x * blockDim.x + threadIdx.x;
    if (e < E_EDGES) {
        int d = ei[E_EDGES + e];
        int pos = atomicAdd(&g_cur[d], 1);
        g_csr_src[pos] = ei[e];
    }
}

// ---------------- GATv2 attention (2 edges/iter) + fused BN partials ----------------
// grid = ATTN_BLOCKS (5000) x 128 threads; warp w handles node blockIdx*4+w (exact cover)
__device__ __forceinline__ void load_row(float* d, int src, int c0) {
    const float4* q = (const float4*)&g_xl[src * HC + c0];
#pragma unroll
    for (int k = 0; k < 4; k++) {
        float4 a = q[k];
        d[4*k+0] = a.x; d[4*k+1] = a.y; d[4*k+2] = a.z; d[4*k+3] = a.w;
    }
}

__global__ void __launch_bounds__(128) attn_kernel(const float* __restrict__ att,
                                                   const float* __restrict__ bias)
{
    __shared__ float srow[4][512];

    const int wid  = threadIdx.x >> 5;
    const int lane = threadIdx.x & 31;
    const int dst  = blockIdx.x * 4 + wid;
    const int c0   = lane * 16;

    float xr_[16], at_[16];
    {
        const float4* p = (const float4*)&g_xr[dst * HC + c0];
        const float4* q = (const float4*)&att[c0];
#pragma unroll
        for (int k = 0; k < 4; k++) {
            float4 a = p[k]; float4 b = q[k];
            xr_[4*k+0] = a.x; xr_[4*k+1] = a.y; xr_[4*k+2] = a.z; xr_[4*k+3] = a.w;
            at_[4*k+0] = b.x; at_[4*k+1] = b.y; at_[4*k+2] = b.z; at_[4*k+3] = b.w;
        }
    }

    float m = -CUDART_INF_F;
    float s = 0.f;
    float acc[16];
#pragma unroll
    for (int j = 0; j < 16; j++) acc[j] = 0.f;

    const int beg = g_off[dst], end = g_off[dst + 1];

    float xl0[16], xl1[16];
    int p = beg;
    if (p < end)     load_row(xl0, g_csr_src[p], c0);
    if (p + 1 < end) load_row(xl1, g_csr_src[p + 1], c0);

    for (; p + 1 < end; p += 2) {
        float xn0[16], xn1[16];
        bool h0 = (p + 2 < end), h1 = (p + 3 < end);
        if (h0) load_row(xn0, g_csr_src[p + 2], c0);
        if (h1) load_row(xn1, g_csr_src[p + 3], c0);

        float part0 = 0.f, part1 = 0.f;
#pragma unroll
        for (int j = 0; j < 16; j++) {
            float v0 = xl0[j] + xr_[j];
            float v1 = xl1[j] + xr_[j];
            float l0 = (v0 > 0.f) ? v0 : 0.2f * v0;
            float l1 = (v1 > 0.f) ? v1 : 0.2f * v1;
            part0 = fmaf(l0, at_[j], part0);
            part1 = fmaf(l1, at_[j], part1);
        }
        part0 += __shfl_xor_sync(0xffffffffu, part0, 1);
        part0 += __shfl_xor_sync(0xffffffffu, part0, 2);
        part1 += __shfl_xor_sync(0xffffffffu, part1, 1);
        part1 += __shfl_xor_sync(0xffffffffu, part1, 2);

        float mnew = fmaxf(m, fmaxf(part0, part1));
        float corr = __expf(m - mnew);
        float w0   = __expf(part0 - mnew);
        float w1   = __expf(part1 - mnew);
        s = s * corr + w0 + w1;
#pragma unroll
        for (int j = 0; j < 16; j++)
            acc[j] = fmaf(xl1[j], w1, fmaf(xl0[j], w0, acc[j] * corr));
        m = mnew;

        if (h0) {
#pragma unroll
            for (int j = 0; j < 16; j++) xl0[j] = xn0[j];
        }
        if (h1) {
#pragma unroll
            for (int j = 0; j < 16; j++) xl1[j] = xn1[j];
        }
    }

    if (p < end) {       // trailing single edge (row already in xl0)
        float part = 0.f;
#pragma unroll
        for (int j = 0; j < 16; j++) {
            float v = xl0[j] + xr_[j];
            float lr = (v > 0.f) ? v : 0.2f * v;
            part = fmaf(lr, at_[j], part);
        }
        part += __shfl_xor_sync(0xffffffffu, part, 1);
        part += __shfl_xor_sync(0xffffffffu, part, 2);
        float mnew = fmaxf(m, part);
        float corr = __expf(m - mnew);
        float w    = __expf(part - mnew);
        s = s * corr + w;
#pragma unroll
        for (int j = 0; j < 16; j++) acc[j] = fmaf(xl0[j], w, acc[j] * corr);
        m = mnew;
    }

    float inv = 1.f / (s + 1e-16f);
    const float4* bq = (const float4*)&bias[c0];
#pragma unroll
    for (int k = 0; k < 4; k++) {
        float4 b = bq[k];
        float4 o;
        o.x = fmaf(acc[4*k+0], inv, b.x);
        o.y = fmaf(acc[4*k+1], inv, b.y);
        o.z = fmaf(acc[4*k+2], inv, b.z);
        o.w = fmaf(acc[4*k+3], inv, b.w);
        *(float4*)&g_out[dst * HC + c0 + 4*k] = o;
        *(float4*)&srow[wid][c0 + 4*k] = o;
    }

    __syncthreads();
    // fixed-order per-block channel reduction: thread t handles channels t+128h
    {
        int t = threadIdx.x;
#pragma unroll
        for (int h = 0; h < 4; h++) {
            int c = t + h * 128;
            float ps = 0.f, pq = 0.f;
#pragma unroll
            for (int w = 0; w < 4; w++) {
                float v = srow[w][c];
                ps += v;
                pq = fmaf(v, v, pq);
            }
            g_ps[blockIdx.x * HC + c] = ps;
            g_pq[blockIdx.x * HC + c] = pq;
        }
    }
}

// ---------------- BN reduction stages ----------------
__global__ void bn_stage1_kernel()      // 128 blocks x 512
{
    int c = threadIdx.x;
    float s = 0.f, ss = 0.f;
    for (int r = blockIdx.x; r < ATTN_BLOCKS; r += BN1_BLOCKS) {
        s  += g_ps[r * HC + c];
        ss += g_pq[r * HC + c];
    }
    g_ps1[blockIdx.x * HC + c] = s;
    g_pq1[blockIdx.x * HC + c] = ss;
}

__global__ void bn_final_kernel(const float* __restrict__ gamma, const float* __restrict__ beta)
{
    int c = threadIdx.x;
    float s = 0.f, ss = 0.f;
    for (int b = 0; b < BN1_BLOCKS; b++) {
        s  += g_ps1[b * HC + c];
        ss += g_pq1[b * HC + c];
    }
    float mu  = s / (float)N_NODES;
    float var = ss / (float)N_NODES - mu * mu;
    float sc  = gamma[c] * rsqrtf(var + 1e-5f);
    g_scale[c] = sc;
    g_shift[c] = beta[c] - mu * sc;
}

// ---------------- link scoring with fused BN+ReLU ----------------
__global__ void link_kernel(const int* __restrict__ eli, float* __restrict__ out)
{
    int w = (blockIdx.x * blockDim.x + threadIdx.x) >> 5;
    int lane = threadIdx.x & 31;
    if (w >= E_LABEL) return;
    int a = eli[w];
    int b = eli[E_LABEL + w];
    const int c0 = lane * 16;
    const float4* pa = (const float4*)&g_out[a * HC + c0];
    const float4* pb = (const float4*)&g_out[b * HC + c0];
    const float4* psc = (const float4*)&g_scale[c0];
    const float4* psh = (const float4*)&g_shift[c0];
    float p = 0.f;
#pragma unroll
    for (int k = 0; k < 4; k++) {
        float4 va = pa[k], vb = pb[k];
        float4 sc = psc[k], sh = psh[k];
        float ax = fmaxf(fmaf(va.x, sc.x, sh.x), 0.f);
        float ay = fmaxf(fmaf(va.y, sc.y, sh.y), 0.f);
        float az = fmaxf(fmaf(va.z, sc.z, sh.z), 0.f);
        float aw = fmaxf(fmaf(va.w, sc.w, sh.w), 0.f);
        float bx = fmaxf(fmaf(vb.x, sc.x, sh.x), 0.f);
        float by = fmaxf(fmaf(vb.y, sc.y, sh.y), 0.f);
        float bz = fmaxf(fmaf(vb.z, sc.z, sh.z), 0.f);
        float bw = fmaxf(fmaf(vb.w, sc.w, sh.w), 0.f);
        p = fmaf(ax, bx, p);
        p = fmaf(ay, by, p);
        p = fmaf(az, bz, p);
        p = fmaf(aw, bw, p);
    }
#pragma unroll
    for (int off = 16; off > 0; off >>= 1)
        p += __shfl_xor_sync(0xffffffffu, p, off);
    if (lane == 0) out[w] = p;
}

// ---------------- launch ----------------
extern "C" void kernel_launch(void* const* d_in, const int* in_sizes, int n_in,
                              void* d_out, int out_size)
{
    const float* x     = (const float*)d_in[0];
    const int*   ei    = (const int*)  d_in[1];
    const int*   eli   = (const int*)  d_in[2];
    const float* W_l   = (const float*)d_in[3];
    const float* W_r   = (const float*)d_in[4];
    const float* att   = (const float*)d_in[5];
    const float* bias  = (const float*)d_in[6];
    const float* gamma = (const float*)d_in[7];
    const float* beta  = (const float*)d_in[8];
    float* out = (float*)d_out;

    static bool s_init = false;
    if (!s_init) {
        cudaFuncSetAttribute(gemm_tc_kernel,
                             cudaFuncAttributeMaxDynamicSharedMemorySize, GSMEM_TOTAL);
        s_init = true;
    }

    // #1 fused conversions (also zeroes g_deg)
    conv_fused_kernel<<<CONVX_BLOCKS + CONVW_BLOCKS, 256>>>(x, W_l, W_r);

    // #2-#3 CSR build front half
    hist_kernel<<<(E_EDGES + 255) / 256, 256>>>(ei);
    scan_blocks_kernel<<<20, 1024>>>();

    // #4 HMMA split-bf16 GEMMs (profiled slot)
    {
        dim3 g(HC / 128, N_PAD / 128, 2);
        gemm_tc_kernel<<<g, 256, GSMEM_TOTAL>>>();
    }

    // #5-#6 CSR build back half
    scan_add_kernel<<<20, 1024>>>();
    scatter_kernel<<<(E_EDGES + 255) / 256, 256>>>(ei);

    // #7 attention + aggregation (+ BN partial sums)
    attn_kernel<<<ATTN_BLOCKS, 128>>>(att, bias);

    // #8-#9 BN reduction
    bn_stage1_kernel<<<BN1_BLOCKS, HC>>>();
    bn_final_kernel<<<1, HC>>>(gamma, beta);

    // #10 link scoring with fused BN + ReLU
    link_kernel<<<(E_LABEL * 32) / 256, 256>>>(eli, out);
}

// round 9
// speedup vs baseline: 1.1864x; 1.0309x over previous
#include <cuda_runtime.h>
#include <cuda_bf16.h>
#include <math_constants.h>
#include <cstdint>

// Problem constants
#define N_NODES 20000
#define N_PAD   20096          // 157 * 128
#define IN_CH   512
#define HC      512
#define HEADS   8
#define CH      64
#define E_EDGES 320000
#define E_LABEL 100000
#define ATTN_BLOCKS 5000       // 20000 nodes / 4 warps per block
#define BN1_BLOCKS 128

// ---------------- scratch ----------------
__device__ __nv_bfloat16 g_xhi[N_PAD * IN_CH];
__device__ __nv_bfloat16 g_xlo[N_PAD * IN_CH];
__device__ __nv_bfloat16 g_wthi[2][IN_CH * HC];
__device__ __nv_bfloat16 g_wtlo[2][IN_CH * HC];
__device__ float g_xl[N_PAD * HC];
__device__ float g_xr[N_PAD * HC];
__device__ __nv_bfloat16 g_xlb[N_PAD * HC];   // bf16 copy of xl for attention gathers
__device__ float g_out[N_NODES * HC];
__device__ int   g_deg[N_NODES + 1];
__device__ int   g_off[N_NODES + 1];
__device__ int   g_cur[N_NODES];
__device__ int   g_csr_src[E_EDGES];
__device__ int   g_bsum[32];
__device__ int   g_bn_cnt;                    // zero-init; self-resetting
__device__ float g_ps [ATTN_BLOCKS * HC];
__device__ float g_pq [ATTN_BLOCKS * HC];
__device__ float g_ps1[BN1_BLOCKS * HC];
__device__ float g_pq1[BN1_BLOCKS * HC];
__device__ float g_scale[HC];
__device__ float g_shift[HC];

// ---------------- helpers ----------------
__device__ __forceinline__ uint32_t smem_u32(const void* p) {
    uint32_t a;
    asm("{ .reg .u64 t; cvta.to.shared.u64 t, %1; cvt.u32.u64 %0, t; }" : "=r"(a) : "l"(p));
    return a;
}
__device__ __forceinline__ void cp_async16(uint32_t sa, const void* ga) {
    asm volatile("cp.async.cg.shared.global [%0], [%1], 16;" :: "r"(sa), "l"(ga) : "memory");
}
__device__ __forceinline__ void cp_commit() {
    asm volatile("cp.async.commit_group;" ::: "memory");
}
__device__ __forceinline__ void cp_wait0() {
    asm volatile("cp.async.wait_group 0;" ::: "memory");
}
__device__ __forceinline__ void ldm_x4(uint32_t* r, uint32_t addr) {
    asm volatile("ldmatrix.sync.aligned.m8n8.x4.shared.b16 {%0,%1,%2,%3}, [%4];"
                 : "=r"(r[0]), "=r"(r[1]), "=r"(r[2]), "=r"(r[3]) : "r"(addr));
}
__device__ __forceinline__ void mma16816(float* d, const uint32_t* a, const uint32_t* b) {
    asm volatile("mma.sync.aligned.m16n8k16.row.col.f32.bf16.bf16.f32 "
                 "{%0,%1,%2,%3}, {%4,%5,%6,%7}, {%8,%9}, {%0,%1,%2,%3};"
                 : "+f"(d[0]), "+f"(d[1]), "+f"(d[2]), "+f"(d[3])
                 : "r"(a[0]), "r"(a[1]), "r"(a[2]), "r"(a[3]), "r"(b[0]), "r"(b[1]));
}
// packed bf16x2 -> two floats (lo, hi) via bit shifts
__device__ __forceinline__ float bflo(uint32_t u) { return __uint_as_float(u << 16); }
__device__ __forceinline__ float bfhi(uint32_t u) { return __uint_as_float(u & 0xFFFF0000u); }

// ---------------- fused conversion ----------------
#define CONVX_BLOCKS (N_PAD * IN_CH / 4 / 256)      // 10048
#define CONVW_BLOCKS (2 * IN_CH * HC / 256)         // 2048

__global__ void conv_fused_kernel(const float* __restrict__ x,
                                  const float* __restrict__ Wl,
                                  const float* __restrict__ Wr)
{
    int bid = blockIdx.x;
    if (bid < CONVX_BLOCKS) {
        int i4 = bid * 256 + threadIdx.x;
        if (i4 <= N_NODES) g_deg[i4] = 0;
        int i = i4 * 4;
        int row = i >> 9;
        float4 v = (row < N_NODES) ? *(const float4*)(x + i) : make_float4(0.f, 0.f, 0.f, 0.f);
        float a[4] = {v.x, v.y, v.z, v.w};
        __nv_bfloat16 h0 = __float2bfloat16(a[0]);
        __nv_bfloat16 h1 = __float2bfloat16(a[1]);
        __nv_bfloat16 h2 = __float2bfloat16(a[2]);
        __nv_bfloat16 h3 = __float2bfloat16(a[3]);
        __nv_bfloat16 l0 = __float2bfloat16(a[0] - __bfloat162float(h0));
        __nv_bfloat16 l1 = __float2bfloat16(a[1] - __bfloat162float(h1));
        __nv_bfloat16 l2 = __float2bfloat16(a[2] - __bfloat162float(h2));
        __nv_bfloat16 l3 = __float2bfloat16(a[3] - __bfloat162float(h3));
        uint32_t hi01 = ((uint32_t)__bfloat16_as_ushort(h1) << 16) | __bfloat16_as_ushort(h0);
        uint32_t hi23 = ((uint32_t)__bfloat16_as_ushort(h3) << 16) | __bfloat16_as_ushort(h2);
        uint32_t lo01 = ((uint32_t)__bfloat16_as_ushort(l1) << 16) | __bfloat16_as_ushort(l0);
        uint32_t lo23 = ((uint32_t)__bfloat16_as_ushort(l3) << 16) | __bfloat16_as_ushort(l2);
        *(uint2*)((char*)g_xhi + i * 2) = make_uint2(hi01, hi23);
        *(uint2*)((char*)g_xlo + i * 2) = make_uint2(lo01, lo23);
    } else {
        int j = (bid - CONVX_BLOCKS) * 256 + threadIdx.x;
        int mat = j >> 18;
        int i = j & 0x3FFFF;                                // n*512 + k
        const float* W = mat ? Wr : Wl;
        int n = i >> 9, k = i & 511;
        float v = W[k * HC + n];
        __nv_bfloat16 h = __float2bfloat16(v);
        g_wthi[mat][i] = h;
        g_wtlo[mat][i] = __float2bfloat16(v - __bfloat162float(h));
    }
}

// ---------------- HMMA split-bf16 GEMM (R8 proven config) ----------------
#define SMS 80
#define TILE_BYTES (128 * SMS)      // 10240
#define STAGE_BYTES (4 * TILE_BYTES)
#define GSMEM_TOTAL (2 * STAGE_BYTES)   // 81920

__global__ void __launch_bounds__(256, 2) gemm_tc_kernel()
{
    extern __shared__ __align__(16) char smem[];

    const int tid  = threadIdx.x;
    const int wid  = tid >> 5;
    const int lane = tid & 31;
    const int wm   = wid & 1;
    const int wn   = wid >> 1;

    const int m0  = blockIdx.y * 128;
    const int n0  = blockIdx.x * 128;
    const int mat = blockIdx.z;

    const __nv_bfloat16* Ah = g_xhi + (size_t)m0 * IN_CH;
    const __nv_bfloat16* Al = g_xlo + (size_t)m0 * IN_CH;
    const __nv_bfloat16* Bh = g_wthi[mat] + (size_t)n0 * IN_CH;
    const __nv_bfloat16* Bl = g_wtlo[mat] + (size_t)n0 * IN_CH;
    float* C = mat ? g_xr : g_xl;

    const uint32_t sb = smem_u32(smem);
    const int r0 = tid >> 2;
    const int c0 = tid & 3;

    float acc[4][4][4];
#pragma unroll
    for (int i = 0; i < 4; i++)
#pragma unroll
        for (int j = 0; j < 4; j++)
#pragma unroll
            for (int q = 0; q < 4; q++) acc[i][j][q] = 0.f;

    auto issue = [&](int kc, int stg) {
        const uint32_t base = sb + stg * STAGE_BYTES;
        const int kel = kc * 32 + c0 * 8;
#pragma unroll
        for (int j = 0; j < 2; j++) {
            int row = r0 + j * 64;
            uint32_t so = row * SMS + c0 * 16;
            size_t  go = (size_t)row * IN_CH + kel;
            cp_async16(base + 0 * TILE_BYTES + so, Ah + go);
            cp_async16(base + 1 * TILE_BYTES + so, Al + go);
            cp_async16(base + 2 * TILE_BYTES + so, Bh + go);
            cp_async16(base + 3 * TILE_BYTES + so, Bl + go);
        }
    };

    issue(0, 0); cp_commit();

    for (int kc = 0; kc < 16; kc++) {
        cp_wait0();
        __syncthreads();
        if (kc + 1 < 16) { issue(kc + 1, (kc + 1) & 1); cp_commit(); }

        const uint32_t base = sb + (kc & 1) * STAGE_BYTES;
#pragma unroll
        for (int ks = 0; ks < 2; ks++) {
            const int kb = ks * 32;
            uint32_t bh[4][2], bl[4][2];
#pragma unroll
            for (int nh = 0; nh < 2; nh++) {
                int row = wn * 32 + nh * 16 + (lane >> 4) * 8 + (lane & 7);
                uint32_t off = row * SMS + kb + ((lane >> 3) & 1) * 16;
                uint32_t t[4];
                ldm_x4(t, base + 2 * TILE_BYTES + off);
                bh[nh * 2 + 0][0] = t[0]; bh[nh * 2 + 0][1] = t[1];
                bh[nh * 2 + 1][0] = t[2]; bh[nh * 2 + 1][1] = t[3];
                ldm_x4(t, base + 3 * TILE_BYTES + off);
                bl[nh * 2 + 0][0] = t[0]; bl[nh * 2 + 0][1] = t[1];
                bl[nh * 2 + 1][0] = t[2]; bl[nh * 2 + 1][1] = t[3];
            }
            uint32_t ah[4][4], al[4][4];
            {
                int row = wm * 64 + ((lane >> 3) & 1) * 8 + (lane & 7);
                uint32_t off = row * SMS + kb + ((lane >> 4) & 1) * 16;
                ldm_x4(ah[0], base + 0 * TILE_BYTES + off);
                ldm_x4(al[0], base + 1 * TILE_BYTES + off);
            }
#pragma unroll
            for (int mt = 0; mt < 4; mt++) {
                if (mt < 3) {
                    int row = wm * 64 + (mt + 1) * 16 + ((lane >> 3) & 1) * 8 + (lane & 7);
                    uint32_t off = row * SMS + kb + ((lane >> 4) & 1) * 16;
                    ldm_x4(ah[mt + 1], base + 0 * TILE_BYTES + off);
                    ldm_x4(al[mt + 1], base + 1 * TILE_BYTES + off);
                }
#pragma unroll
                for (int nt = 0; nt < 4; nt++) {
                    mma16816(acc[mt][nt], ah[mt], bh[nt]);
                    mma16816(acc[mt][nt], ah[mt], bl[nt]);
                    mma16816(acc[mt][nt], al[mt], bh[nt]);
                }
            }
        }
    }

    const int g = lane >> 2;
    const int q = lane & 3;
#pragma unroll
    for (int mt = 0; mt < 4; mt++) {
#pragma unroll
        for (int nt = 0; nt < 4; nt++) {
            int row = m0 + wm * 64 + mt * 16 + g;
            int col = n0 + wn * 32 + nt * 8 + q * 2;
            float2 v0 = make_float2(acc[mt][nt][0], acc[mt][nt][1]);
            float2 v1 = make_float2(acc[mt][nt][2], acc[mt][nt][3]);
            *(float2*)&C[(size_t)row * HC + col] = v0;
            *(float2*)&C[(size_t)(row + 8) * HC + col] = v1;
            if (mat == 0) {   // bf16 copy for attention gathers
                __nv_bfloat162 b0 = __float22bfloat162_rn(v0);
                __nv_bfloat162 b1 = __float22bfloat162_rn(v1);
                *(__nv_bfloat162*)&g_xlb[(size_t)row * HC + col] = b0;
                *(__nv_bfloat162*)&g_xlb[(size_t)(row + 8) * HC + col] = b1;
            }
        }
    }
}

// ---------------- CSR build ----------------
__global__ void hist_kernel(const int* __restrict__ ei)
{
    int e = blockIdx.x * blockDim.x + threadIdx.x;
    if (e < E_EDGES) atomicAdd(&g_deg[ei[E_EDGES + e]], 1);
}

__global__ void scan_blocks_kernel()     // 20 blocks x 1024
{
    __shared__ int wsum[32];
    int b = blockIdx.x, t = threadIdx.x;
    int i = b * 1024 + t;
    int v = (i < N_NODES) ? g_deg[i] : 0;
    int lane = t & 31, w = t >> 5;
    int s = v;
#pragma unroll
    for (int o = 1; o < 32; o <<= 1) {
        int u = __shfl_up_sync(0xffffffffu, s, o);
        if (lane >= o) s += u;
    }
    if (lane == 31) wsum[w] = s;
    __syncthreads();
    if (w == 0) {
        int ws = wsum[lane];
#pragma unroll
        for (int o = 1; o < 32; o <<= 1) {
            int u = __shfl_up_sync(0xffffffffu, ws, o);
            if (lane >= o) ws += u;
        }
        wsum[lane] = ws;
    }
    __syncthreads();
    int excl = s - v + (w > 0 ? wsum[w - 1] : 0);
    if (i < N_NODES) g_off[i] = excl;
    if (t == 1023) g_bsum[b] = excl + v;
}

__global__ void scan_add_kernel()        // 20 blocks x 1024
{
    __shared__ int boff;
    int b = blockIdx.x, t = threadIdx.x;
    if (t == 0) {
        int s = 0;
        for (int j = 0; j < b; j++) s += g_bsum[j];
        boff = s;
    }
    __syncthreads();
    int i = b * 1024 + t;
    if (i < N_NODES) {
        int o = g_off[i] + boff;
        g_off[i] = o;
        g_cur[i] = o;
    }
    if (i == 0) g_off[N_NODES] = E_EDGES;
}

__global__ void scatter_kernel(const int* __restrict__ ei)
{
    int e = blockIdx.x * blockDim.x + threadIdx.x;
    if (e < E_EDGES) {
        int d = ei[E_EDGES + e];
        int pos = atomicAdd(&g_cur[d], 1);
        g_csr_src[pos] = ei[e];
    }
}

// ---------------- GATv2 attention: bf16 rows, 4-edge pipeline + fused BN partials ----------------
__device__ __forceinline__ void load_row_bf(uint32_t* d, int src, int c0) {
    const uint4* q = (const uint4*)&g_xlb[src * HC + c0];
    uint4 a = q[0], b = q[1];
    d[0] = a.x; d[1] = a.y; d[2] = a.z; d[3] = a.w;
    d[4] = b.x; d[5] = b.y; d[6] = b.z; d[7] = b.w;
}

__global__ void __launch_bounds__(128) attn_kernel(const float* __restrict__ att,
                                                   const float* __restrict__ bias)
{
    __shared__ float srow[4][512];

    const int wid  = threadIdx.x >> 5;
    const int lane = threadIdx.x & 31;
    const int dst  = blockIdx.x * 4 + wid;
    const int c0   = lane * 16;

    float xr_[16], at_[16];
    {
        const float4* p = (const float4*)&g_xr[dst * HC + c0];
        const float4* q = (const float4*)&att[c0];
#pragma unroll
        for (int k = 0; k < 4; k++) {
            float4 a = p[k]; float4 b = q[k];
            xr_[4*k+0] = a.x; xr_[4*k+1] = a.y; xr_[4*k+2] = a.z; xr_[4*k+3] = a.w;
            at_[4*k+0] = b.x; at_[4*k+1] = b.y; at_[4*k+2] = b.z; at_[4*k+3] = b.w;
        }
    }

    float m = -CUDART_INF_F;
    float s = 0.f;
    float acc[16];
#pragma unroll
    for (int j = 0; j < 16; j++) acc[j] = 0.f;

    const int beg = g_off[dst], end = g_off[dst + 1];

    uint32_t cur[4][8], nxt[4][8];
    if (beg < end) {
#pragma unroll
        for (int i = 0; i < 4; i++) {
            int idx = beg + i; if (idx > end - 1) idx = end - 1;
            load_row_bf(cur[i], g_csr_src[idx], c0);
        }
    }

    for (int p = beg; p < end; p += 4) {
        bool have_next = (p + 4 < end);
        if (have_next) {
#pragma unroll
            for (int i = 0; i < 4; i++) {
                int idx = p + 4 + i; if (idx > end - 1) idx = end - 1;
                load_row_bf(nxt[i], g_csr_src[idx], c0);
            }
        }

        float part[4];
#pragma unroll
        for (int i = 0; i < 4; i++) {
            float pt = 0.f;
#pragma unroll
            for (int j8 = 0; j8 < 8; j8++) {
                float x0 = bflo(cur[i][j8]);
                float x1 = bfhi(cur[i][j8]);
                float v0 = x0 + xr_[2*j8+0];
                float v1 = x1 + xr_[2*j8+1];
                float l0 = (v0 > 0.f) ? v0 : 0.2f * v0;
                float l1 = (v1 > 0.f) ? v1 : 0.2f * v1;
                pt = fmaf(l0, at_[2*j8+0], pt);
                pt = fmaf(l1, at_[2*j8+1], pt);
            }
            pt += __shfl_xor_sync(0xffffffffu, pt, 1);
            pt += __shfl_xor_sync(0xffffffffu, pt, 2);
            part[i] = (p + i < end) ? pt : -CUDART_INF_F;
        }

        float gm = fmaxf(fmaxf(part[0], part[1]), fmaxf(part[2], part[3]));
        float mnew = fmaxf(m, gm);
        float corr = __expf(m - mnew);
        float w[4];
#pragma unroll
        for (int i = 0; i < 4; i++) w[i] = __expf(part[i] - mnew);
        s = s * corr + w[0] + w[1] + w[2] + w[3];
#pragma unroll
        for (int j8 = 0; j8 < 8; j8++) {
            float t0 = acc[2*j8+0] * corr;
            float t1 = acc[2*j8+1] * corr;
#pragma unroll
            for (int i = 0; i < 4; i++) {
                t0 = fmaf(bflo(cur[i][j8]), w[i], t0);
                t1 = fmaf(bfhi(cur[i][j8]), w[i], t1);
            }
            acc[2*j8+0] = t0;
            acc[2*j8+1] = t1;
        }
        m = mnew;

        if (have_next) {
#pragma unroll
            for (int i = 0; i < 4; i++)
#pragma unroll
                for (int j8 = 0; j8 < 8; j8++) cur[i][j8] = nxt[i][j8];
        }
    }

    float inv = 1.f / (s + 1e-16f);
    const float4* bq = (const float4*)&bias[c0];
#pragma unroll
    for (int k = 0; k < 4; k++) {
        float4 b = bq[k];
        float4 o;
        o.x = fmaf(acc[4*k+0], inv, b.x);
        o.y = fmaf(acc[4*k+1], inv, b.y);
        o.z = fmaf(acc[4*k+2], inv, b.z);
        o.w = fmaf(acc[4*k+3], inv, b.w);
        *(float4*)&g_out[dst * HC + c0 + 4*k] = o;
        *(float4*)&srow[wid][c0 + 4*k] = o;
    }

    __syncthreads();
    {
        int t = threadIdx.x;
#pragma unroll
        for (int h = 0; h < 4; h++) {
            int c = t + h * 128;
            float ps = 0.f, pq = 0.f;
#pragma unroll
            for (int w2 = 0; w2 < 4; w2++) {
                float v = srow[w2][c];
                ps += v;
                pq = fmaf(v, v, pq);
            }
            g_ps[blockIdx.x * HC + c] = ps;
            g_pq[blockIdx.x * HC + c] = pq;
        }
    }
}

// ---------------- merged BN reduction (last-block pattern, deterministic) ----------------
__global__ void bn_reduce_kernel(const float* __restrict__ gamma, const float* __restrict__ beta)
{
    int c = threadIdx.x;
    float s = 0.f, ss = 0.f;
    for (int r = blockIdx.x; r < ATTN_BLOCKS; r += BN1_BLOCKS) {
        s  += g_ps[r * HC + c];
        ss += g_pq[r * HC + c];
    }
    g_ps1[blockIdx.x * HC + c] = s;
    g_pq1[blockIdx.x * HC + c] = ss;
    __threadfence();

    __shared__ int last;
    if (threadIdx.x == 0) {
        int v = atomicAdd(&g_bn_cnt, 1);
        last = (v == BN1_BLOCKS - 1);
    }
    __syncthreads();
    if (last) {
        float t = 0.f, tt = 0.f;
        for (int b = 0; b < BN1_BLOCKS; b++) {
            t  += g_ps1[b * HC + c];
            tt += g_pq1[b * HC + c];
        }
        float mu  = t / (float)N_NODES;
        float var = tt / (float)N_NODES - mu * mu;
        float sc  = gamma[c] * rsqrtf(var + 1e-5f);
        g_scale[c] = sc;
        g_shift[c] = beta[c] - mu * sc;
        if (threadIdx.x == 0) g_bn_cnt = 0;   // reset for next graph replay
    }
}

// ---------------- link scoring with fused BN+ReLU ----------------
__global__ void link_kernel(const int* __restrict__ eli, float* __restrict__ out)
{
    int w = (blockIdx.x * blockDim.x + threadIdx.x) >> 5;
    int lane = threadIdx.x & 31;
    if (w >= E_LABEL) return;
    int a = eli[w];
    int b = eli[E_LABEL + w];
    const int c0 = lane * 16;
    const float4* pa = (const float4*)&g_out[a * HC + c0];
    const float4* pb = (const float4*)&g_out[b * HC + c0];
    const float4* psc = (const float4*)&g_scale[c0];
    const float4* psh = (const float4*)&g_shift[c0];
    float p = 0.f;
#pragma unroll
    for (int k = 0; k < 4; k++) {
        float4 va = pa[k], vb = pb[k];
        float4 sc = psc[k], sh = psh[k];
        float ax = fmaxf(fmaf(va.x, sc.x, sh.x), 0.f);
        float ay = fmaxf(fmaf(va.y, sc.y, sh.y), 0.f);
        float az = fmaxf(fmaf(va.z, sc.z, sh.z), 0.f);
        float aw = fmaxf(fmaf(va.w, sc.w, sh.w), 0.f);
        float bx = fmaxf(fmaf(vb.x, sc.x, sh.x), 0.f);
        float by = fmaxf(fmaf(vb.y, sc.y, sh.y), 0.f);
        float bz = fmaxf(fmaf(vb.z, sc.z, sh.z), 0.f);
        float bw = fmaxf(fmaf(vb.w, sc.w, sh.w), 0.f);
        p = fmaf(ax, bx, p);
        p = fmaf(ay, by, p);
        p = fmaf(az, bz, p);
        p = fmaf(aw, bw, p);
    }
#pragma unroll
    for (int off = 16; off > 0; off >>= 1)
        p += __shfl_xor_sync(0xffffffffu, p, off);
    if (lane == 0) out[w] = p;
}

// ---------------- launch ----------------
extern "C" void kernel_launch(void* const* d_in, const int* in_sizes, int n_in,
                              void* d_out, int out_size)
{
    const float* x     = (const float*)d_in[0];
    const int*   ei    = (const int*)  d_in[1];
    const int*   eli   = (const int*)  d_in[2];
    const float* W_l   = (const float*)d_in[3];
    const float* W_r   = (const float*)d_in[4];
    const float* att   = (const float*)d_in[5];
    const float* bias  = (const float*)d_in[6];
    const float* gamma = (const float*)d_in[7];
    const float* beta  = (const float*)d_in[8];
    float* out = (float*)d_out;

    static bool s_init = false;
    if (!s_init) {
        cudaFuncSetAttribute(gemm_tc_kernel,
                             cudaFuncAttributeMaxDynamicSharedMemorySize, GSMEM_TOTAL);
        s_init = true;
    }

    // #1 fused conversions (also zeroes g_deg)
    conv_fused_kernel<<<CONVX_BLOCKS + CONVW_BLOCKS, 256>>>(x, W_l, W_r);

    // #2-#3 CSR build front half
    hist_kernel<<<(E_EDGES + 255) / 256, 256>>>(ei);
    scan_blocks_kernel<<<20, 1024>>>();

    // #4 HMMA split-bf16 GEMMs (profiled slot)
    {
        dim3 g(HC / 128, N_PAD / 128, 2);
        gemm_tc_kernel<<<g, 256, GSMEM_TOTAL>>>();
    }

    // #5-#6 CSR build back half
    scan_add_kernel<<<20, 1024>>>();
    scatter_kernel<<<(E_EDGES + 255) / 256, 256>>>(ei);

    // #7 attention + aggregation (+ BN partial sums)
    attn_kernel<<<ATTN_BLOCKS, 128>>>(att, bias);

    // #8 merged BN reduction
    bn_reduce_kernel<<<BN1_BLOCKS, HC>>>(gamma, beta);

    // #9 link scoring with fused BN + ReLU
    link_kernel<<<(E_LABEL * 32) / 256, 256>>>(eli, out);
}

// round 10
// speedup vs baseline: 1.3168x; 1.1099x over previous
#include <cuda_runtime.h>
#include <cuda_bf16.h>
#include <math_constants.h>
#include <cstdint>

// Problem constants
#define N_NODES 20000
#define N_PAD   20096          // 157 * 128
#define IN_CH   512
#define HC      512
#define HEADS   8
#define CH      64
#define E_EDGES 320000
#define E_LABEL 100000
#define ATTN_BLOCKS 5000       // 20000 nodes / 4 warps per block
#define BN1_BLOCKS 128

// ---------------- scratch ----------------
__device__ __nv_bfloat16 g_xhi[N_PAD * IN_CH];
__device__ __nv_bfloat16 g_xlo[N_PAD * IN_CH];
__device__ __nv_bfloat16 g_wthi[2][IN_CH * HC];
__device__ __nv_bfloat16 g_wtlo[2][IN_CH * HC];
__device__ float g_xr[N_PAD * HC];
__device__ __nv_bfloat16 g_xlb[N_PAD * HC];    // bf16 xl (only copy; fp32 xl was dead)
__device__ __nv_bfloat16 g_outb[N_NODES * HC]; // bf16 node features after GAT
__device__ int   g_deg[N_NODES + 1];
__device__ int   g_off[N_NODES + 1];
__device__ int   g_cur[N_NODES];
__device__ int   g_csr_src[E_EDGES];
__device__ int   g_bsum[32];
__device__ int   g_bn_cnt;                     // zero-init; self-resetting
__device__ float g_ps [ATTN_BLOCKS * HC];
__device__ float g_pq [ATTN_BLOCKS * HC];
__device__ float g_ps1[BN1_BLOCKS * HC];
__device__ float g_pq1[BN1_BLOCKS * HC];
__device__ float g_scale[HC];
__device__ float g_shift[HC];

// ---------------- helpers ----------------
__device__ __forceinline__ uint32_t smem_u32(const void* p) {
    uint32_t a;
    asm("{ .reg .u64 t; cvta.to.shared.u64 t, %1; cvt.u32.u64 %0, t; }" : "=r"(a) : "l"(p));
    return a;
}
__device__ __forceinline__ void cp_async16(uint32_t sa, const void* ga) {
    asm volatile("cp.async.cg.shared.global [%0], [%1], 16;" :: "r"(sa), "l"(ga) : "memory");
}
__device__ __forceinline__ void cp_commit() {
    asm volatile("cp.async.commit_group;" ::: "memory");
}
__device__ __forceinline__ void cp_wait0() {
    asm volatile("cp.async.wait_group 0;" ::: "memory");
}
__device__ __forceinline__ void ldm_x4(uint32_t* r, uint32_t addr) {
    asm volatile("ldmatrix.sync.aligned.m8n8.x4.shared.b16 {%0,%1,%2,%3}, [%4];"
                 : "=r"(r[0]), "=r"(r[1]), "=r"(r[2]), "=r"(r[3]) : "r"(addr));
}
__device__ __forceinline__ void mma16816(float* d, const uint32_t* a, const uint32_t* b) {
    asm volatile("mma.sync.aligned.m16n8k16.row.col.f32.bf16.bf16.f32 "
                 "{%0,%1,%2,%3}, {%4,%5,%6,%7}, {%8,%9}, {%0,%1,%2,%3};"
                 : "+f"(d[0]), "+f"(d[1]), "+f"(d[2]), "+f"(d[3])
                 : "r"(a[0]), "r"(a[1]), "r"(a[2]), "r"(a[3]), "r"(b[0]), "r"(b[1]));
}
__device__ __forceinline__ float bflo(uint32_t u) { return __uint_as_float(u << 16); }
__device__ __forceinline__ float bfhi(uint32_t u) { return __uint_as_float(u & 0xFFFF0000u); }
__device__ __forceinline__ uint32_t packbf(float a, float b) {
    __nv_bfloat162 t = __float22bfloat162_rn(make_float2(a, b));
    return *(uint32_t*)&t;
}

// ---------------- fused conversion ----------------
#define CONVX_BLOCKS (N_PAD * IN_CH / 4 / 256)      // 10048
#define CONVW_BLOCKS (2 * IN_CH * HC / 256)         // 2048

__global__ void conv_fused_kernel(const float* __restrict__ x,
                                  const float* __restrict__ Wl,
                                  const float* __restrict__ Wr)
{
    int bid = blockIdx.x;
    if (bid < CONVX_BLOCKS) {
        int i4 = bid * 256 + threadIdx.x;
        if (i4 <= N_NODES) g_deg[i4] = 0;
        int i = i4 * 4;
        int row = i >> 9;
        float4 v = (row < N_NODES) ? *(const float4*)(x + i) : make_float4(0.f, 0.f, 0.f, 0.f);
        float a[4] = {v.x, v.y, v.z, v.w};
        __nv_bfloat16 h0 = __float2bfloat16(a[0]);
        __nv_bfloat16 h1 = __float2bfloat16(a[1]);
        __nv_bfloat16 h2 = __float2bfloat16(a[2]);
        __nv_bfloat16 h3 = __float2bfloat16(a[3]);
        __nv_bfloat16 l0 = __float2bfloat16(a[0] - __bfloat162float(h0));
        __nv_bfloat16 l1 = __float2bfloat16(a[1] - __bfloat162float(h1));
        __nv_bfloat16 l2 = __float2bfloat16(a[2] - __bfloat162float(h2));
        __nv_bfloat16 l3 = __float2bfloat16(a[3] - __bfloat162float(h3));
        uint32_t hi01 = ((uint32_t)__bfloat16_as_ushort(h1) << 16) | __bfloat16_as_ushort(h0);
        uint32_t hi23 = ((uint32_t)__bfloat16_as_ushort(h3) << 16) | __bfloat16_as_ushort(h2);
        uint32_t lo01 = ((uint32_t)__bfloat16_as_ushort(l1) << 16) | __bfloat16_as_ushort(l0);
        uint32_t lo23 = ((uint32_t)__bfloat16_as_ushort(l3) << 16) | __bfloat16_as_ushort(l2);
        *(uint2*)((char*)g_xhi + i * 2) = make_uint2(hi01, hi23);
        *(uint2*)((char*)g_xlo + i * 2) = make_uint2(lo01, lo23);
    } else {
        int j = (bid - CONVX_BLOCKS) * 256 + threadIdx.x;
        int mat = j >> 18;
        int i = j & 0x3FFFF;                                // n*512 + k
        const float* W = mat ? Wr : Wl;
        int n = i >> 9, k = i & 511;
        float v = W[k * HC + n];
        __nv_bfloat16 h = __float2bfloat16(v);
        g_wthi[mat][i] = h;
        g_wtlo[mat][i] = __float2bfloat16(v - __bfloat162float(h));
    }
}

// ---------------- HMMA split-bf16 GEMM (frozen R8 config; epilogue writes bf16 for xl) ----------------
#define SMS 80
#define TILE_BYTES (128 * SMS)      // 10240
#define STAGE_BYTES (4 * TILE_BYTES)
#define GSMEM_TOTAL (2 * STAGE_BYTES)   // 81920

__global__ void __launch_bounds__(256, 2) gemm_tc_kernel()
{
    extern __shared__ __align__(16) char smem[];

    const int tid  = threadIdx.x;
    const int wid  = tid >> 5;
    const int lane = tid & 31;
    const int wm   = wid & 1;
    const int wn   = wid >> 1;

    const int m0  = blockIdx.y * 128;
    const int n0  = blockIdx.x * 128;
    const int mat = blockIdx.z;

    const __nv_bfloat16* Ah = g_xhi + (size_t)m0 * IN_CH;
    const __nv_bfloat16* Al = g_xlo + (size_t)m0 * IN_CH;
    const __nv_bfloat16* Bh = g_wthi[mat] + (size_t)n0 * IN_CH;
    const __nv_bfloat16* Bl = g_wtlo[mat] + (size_t)n0 * IN_CH;

    const uint32_t sb = smem_u32(smem);
    const int r0 = tid >> 2;
    const int c0 = tid & 3;

    float acc[4][4][4];
#pragma unroll
    for (int i = 0; i < 4; i++)
#pragma unroll
        for (int j = 0; j < 4; j++)
#pragma unroll
            for (int q = 0; q < 4; q++) acc[i][j][q] = 0.f;

    auto issue = [&](int kc, int stg) {
        const uint32_t base = sb + stg * STAGE_BYTES;
        const int kel = kc * 32 + c0 * 8;
#pragma unroll
        for (int j = 0; j < 2; j++) {
            int row = r0 + j * 64;
            uint32_t so = row * SMS + c0 * 16;
            size_t  go = (size_t)row * IN_CH + kel;
            cp_async16(base + 0 * TILE_BYTES + so, Ah + go);
            cp_async16(base + 1 * TILE_BYTES + so, Al + go);
            cp_async16(base + 2 * TILE_BYTES + so, Bh + go);
            cp_async16(base + 3 * TILE_BYTES + so, Bl + go);
        }
    };

    issue(0, 0); cp_commit();

    for (int kc = 0; kc < 16; kc++) {
        cp_wait0();
        __syncthreads();
        if (kc + 1 < 16) { issue(kc + 1, (kc + 1) & 1); cp_commit(); }

        const uint32_t base = sb + (kc & 1) * STAGE_BYTES;
#pragma unroll
        for (int ks = 0; ks < 2; ks++) {
            const int kb = ks * 32;
            uint32_t bh[4][2], bl[4][2];
#pragma unroll
            for (int nh = 0; nh < 2; nh++) {
                int row = wn * 32 + nh * 16 + (lane >> 4) * 8 + (lane & 7);
                uint32_t off = row * SMS + kb + ((lane >> 3) & 1) * 16;
                uint32_t t[4];
                ldm_x4(t, base + 2 * TILE_BYTES + off);
                bh[nh * 2 + 0][0] = t[0]; bh[nh * 2 + 0][1] = t[1];
                bh[nh * 2 + 1][0] = t[2]; bh[nh * 2 + 1][1] = t[3];
                ldm_x4(t, base + 3 * TILE_BYTES + off);
                bl[nh * 2 + 0][0] = t[0]; bl[nh * 2 + 0][1] = t[1];
                bl[nh * 2 + 1][0] = t[2]; bl[nh * 2 + 1][1] = t[3];
            }
            uint32_t ah[4][4], al[4][4];
            {
                int row = wm * 64 + ((lane >> 3) & 1) * 8 + (lane & 7);
                uint32_t off = row * SMS + kb + ((lane >> 4) & 1) * 16;
                ldm_x4(ah[0], base + 0 * TILE_BYTES + off);
                ldm_x4(al[0], base + 1 * TILE_BYTES + off);
            }
#pragma unroll
            for (int mt = 0; mt < 4; mt++) {
                if (mt < 3) {
                    int row = wm * 64 + (mt + 1) * 16 + ((lane >> 3) & 1) * 8 + (lane & 7);
                    uint32_t off = row * SMS + kb + ((lane >> 4) & 1) * 16;
                    ldm_x4(ah[mt + 1], base + 0 * TILE_BYTES + off);
                    ldm_x4(al[mt + 1], base + 1 * TILE_BYTES + off);
                }
#pragma unroll
                for (int nt = 0; nt < 4; nt++) {
                    mma16816(acc[mt][nt], ah[mt], bh[nt]);
                    mma16816(acc[mt][nt], ah[mt], bl[nt]);
                    mma16816(acc[mt][nt], al[mt], bh[nt]);
                }
            }
        }
    }

    const int g = lane >> 2;
    const int q = lane & 3;
#pragma unroll
    for (int mt = 0; mt < 4; mt++) {
#pragma unroll
        for (int nt = 0; nt < 4; nt++) {
            int row = m0 + wm * 64 + mt * 16 + g;
            int col = n0 + wn * 32 + nt * 8 + q * 2;
            if (mat == 0) {
                // xl: bf16 only (fp32 copy was never read)
                *(uint32_t*)&g_xlb[(size_t)row * HC + col] =
                    packbf(acc[mt][nt][0], acc[mt][nt][1]);
                *(uint32_t*)&g_xlb[(size_t)(row + 8) * HC + col] =
                    packbf(acc[mt][nt][2], acc[mt][nt][3]);
            } else {
                *(float2*)&g_xr[(size_t)row * HC + col] =
                    make_float2(acc[mt][nt][0], acc[mt][nt][1]);
                *(float2*)&g_xr[(size_t)(row + 8) * HC + col] =
                    make_float2(acc[mt][nt][2], acc[mt][nt][3]);
            }
        }
    }
}

// ---------------- CSR build ----------------
__global__ void hist_kernel(const int* __restrict__ ei)
{
    int e = blockIdx.x * blockDim.x + threadIdx.x;
    if (e < E_EDGES) atomicAdd(&g_deg[ei[E_EDGES + e]], 1);
}

__global__ void scan_blocks_kernel()     // 20 blocks x 1024
{
    __shared__ int wsum[32];
    int b = blockIdx.x, t = threadIdx.x;
    int i = b * 1024 + t;
    int v = (i < N_NODES) ? g_deg[i] : 0;
    int lane = t & 31, w = t >> 5;
    int s = v;
#pragma unroll
    for (int o = 1; o < 32; o <<= 1) {
        int u = __shfl_up_sync(0xffffffffu, s, o);
        if (lane >= o) s += u;
    }
    if (lane == 31) wsum[w] = s;
    __syncthreads();
    if (w == 0) {
        int ws = wsum[lane];
#pragma unroll
        for (int o = 1; o < 32; o <<= 1) {
            int u = __shfl_up_sync(0xffffffffu, ws, o);
            if (lane >= o) ws += u;
        }
        wsum[lane] = ws;
    }
    __syncthreads();
    int excl = s - v + (w > 0 ? wsum[w - 1] : 0);
    if (i < N_NODES) g_off[i] = excl;
    if (t == 1023) g_bsum[b] = excl + v;
}

__global__ void scan_add_kernel()        // 20 blocks x 1024
{
    __shared__ int boff;
    int b = blockIdx.x, t = threadIdx.x;
    if (t == 0) {
        int s = 0;
        for (int j = 0; j < b; j++) s += g_bsum[j];
        boff = s;
    }
    __syncthreads();
    int i = b * 1024 + t;
    if (i < N_NODES) {
        int o = g_off[i] + boff;
        g_off[i] = o;
        g_cur[i] = o;
    }
    if (i == 0) g_off[N_NODES] = E_EDGES;
}

__global__ void scatter_kernel(const int* __restrict__ ei)
{
    int e = blockIdx.x * blockDim.x + threadIdx.x;
    if (e < E_EDGES) {
        int d = ei[E_EDGES + e];
        int pos = atomicAdd(&g_cur[d], 1);
        g_csr_src[pos] = ei[e];
    }
}

// ---------------- GATv2 attention: bf16 rows, 4-edge pipeline + fused BN partials ----------------
__device__ __forceinline__ void load_row_bf(uint32_t* d, int src, int c0) {
    const uint4* q = (const uint4*)&g_xlb[src * HC + c0];
    uint4 a = q[0], b = q[1];
    d[0] = a.x; d[1] = a.y; d[2] = a.z; d[3] = a.w;
    d[4] = b.x; d[5] = b.y; d[6] = b.z; d[7] = b.w;
}

__global__ void __launch_bounds__(128) attn_kernel(const float* __restrict__ att,
                                                   const float* __restrict__ bias)
{
    __shared__ float srow[4][512];

    const int wid  = threadIdx.x >> 5;
    const int lane = threadIdx.x & 31;
    const int dst  = blockIdx.x * 4 + wid;
    const int c0   = lane * 16;

    float xr_[16], at_[16];
    {
        const float4* p = (const float4*)&g_xr[dst * HC + c0];
        const float4* q = (const float4*)&att[c0];
#pragma unroll
        for (int k = 0; k < 4; k++) {
            float4 a = p[k]; float4 b = q[k];
            xr_[4*k+0] = a.x; xr_[4*k+1] = a.y; xr_[4*k+2] = a.z; xr_[4*k+3] = a.w;
            at_[4*k+0] = b.x; at_[4*k+1] = b.y; at_[4*k+2] = b.z; at_[4*k+3] = b.w;
        }
    }

    float m = -CUDART_INF_F;
    float s = 0.f;
    float acc[16];
#pragma unroll
    for (int j = 0; j < 16; j++) acc[j] = 0.f;

    const int beg = g_off[dst], end = g_off[dst + 1];

    uint32_t cur[4][8], nxt[4][8];
    if (beg < end) {
#pragma unroll
        for (int i = 0; i < 4; i++) {
            int idx = beg + i; if (idx > end - 1) idx = end - 1;
            load_row_bf(cur[i], g_csr_src[idx], c0);
        }
    }

    for (int p = beg; p < end; p += 4) {
        bool have_next = (p + 4 < end);
        if (have_next) {
#pragma unroll
            for (int i = 0; i < 4; i++) {
                int idx = p + 4 + i; if (idx > end - 1) idx = end - 1;
                load_row_bf(nxt[i], g_csr_src[idx], c0);
            }
        }

        float part[4];
#pragma unroll
        for (int i = 0; i < 4; i++) {
            float pt = 0.f;
#pragma unroll
            for (int j8 = 0; j8 < 8; j8++) {
                float x0 = bflo(cur[i][j8]);
                float x1 = bfhi(cur[i][j8]);
                float v0 = x0 + xr_[2*j8+0];
                float v1 = x1 + xr_[2*j8+1];
                float l0 = (v0 > 0.f) ? v0 : 0.2f * v0;
                float l1 = (v1 > 0.f) ? v1 : 0.2f * v1;
                pt = fmaf(l0, at_[2*j8+0], pt);
                pt = fmaf(l1, at_[2*j8+1], pt);
            }
            pt += __shfl_xor_sync(0xffffffffu, pt, 1);
            pt += __shfl_xor_sync(0xffffffffu, pt, 2);
            part[i] = (p + i < end) ? pt : -CUDART_INF_F;
        }

        float gm = fmaxf(fmaxf(part[0], part[1]), fmaxf(part[2], part[3]));
        float mnew = fmaxf(m, gm);
        float corr = __expf(m - mnew);
        float w[4];
#pragma unroll
        for (int i = 0; i < 4; i++) w[i] = __expf(part[i] - mnew);
        s = s * corr + w[0] + w[1] + w[2] + w[3];
#pragma unroll
        for (int j8 = 0; j8 < 8; j8++) {
            float t0 = acc[2*j8+0] * corr;
            float t1 = acc[2*j8+1] * corr;
#pragma unroll
            for (int i = 0; i < 4; i++) {
                t0 = fmaf(bflo(cur[i][j8]), w[i], t0);
                t1 = fmaf(bfhi(cur[i][j8]), w[i], t1);
            }
            acc[2*j8+0] = t0;
            acc[2*j8+1] = t1;
        }
        m = mnew;

        if (have_next) {
#pragma unroll
            for (int i = 0; i < 4; i++)
#pragma unroll
                for (int j8 = 0; j8 < 8; j8++) cur[i][j8] = nxt[i][j8];
        }
    }

    float inv = 1.f / (s + 1e-16f);
    const float4* bq = (const float4*)&bias[c0];
    uint32_t ob[8];
#pragma unroll
    for (int k = 0; k < 4; k++) {
        float4 b = bq[k];
        float4 o;
        o.x = fmaf(acc[4*k+0], inv, b.x);
        o.y = fmaf(acc[4*k+1], inv, b.y);
        o.z = fmaf(acc[4*k+2], inv, b.z);
        o.w = fmaf(acc[4*k+3], inv, b.w);
        *(float4*)&srow[wid][c0 + 4*k] = o;
        ob[2*k + 0] = packbf(o.x, o.y);
        ob[2*k + 1] = packbf(o.z, o.w);
    }
    *(uint4*)&g_outb[dst * HC + c0]     = make_uint4(ob[0], ob[1], ob[2], ob[3]);
    *(uint4*)&g_outb[dst * HC + c0 + 8] = make_uint4(ob[4], ob[5], ob[6], ob[7]);

    __syncthreads();
    {
        int t = threadIdx.x;
#pragma unroll
        for (int h = 0; h < 4; h++) {
            int c = t + h * 128;
            float ps = 0.f, pq = 0.f;
#pragma unroll
            for (int w2 = 0; w2 < 4; w2++) {
                float v = srow[w2][c];
                ps += v;
                pq = fmaf(v, v, pq);
            }
            g_ps[blockIdx.x * HC + c] = ps;
            g_pq[blockIdx.x * HC + c] = pq;
        }
    }
}

// ---------------- merged BN reduction (last-block pattern, deterministic) ----------------
__global__ void bn_reduce_kernel(const float* __restrict__ gamma, const float* __restrict__ beta)
{
    int c = threadIdx.x;
    float s = 0.f, ss = 0.f;
    for (int r = blockIdx.x; r < ATTN_BLOCKS; r += BN1_BLOCKS) {
        s  += g_ps[r * HC + c];
        ss += g_pq[r * HC + c];
    }
    g_ps1[blockIdx.x * HC + c] = s;
    g_pq1[blockIdx.x * HC + c] = ss;
    __threadfence();

    __shared__ int last;
    if (threadIdx.x == 0) {
        int v = atomicAdd(&g_bn_cnt, 1);
        last = (v == BN1_BLOCKS - 1);
    }
    __syncthreads();
    if (last) {
        float t = 0.f, tt = 0.f;
        for (int b = 0; b < BN1_BLOCKS; b++) {
            t  += g_ps1[b * HC + c];
            tt += g_pq1[b * HC + c];
        }
        float mu  = t / (float)N_NODES;
        float var = tt / (float)N_NODES - mu * mu;
        float sc  = gamma[c] * rsqrtf(var + 1e-5f);
        g_scale[c] = sc;
        g_shift[c] = beta[c] - mu * sc;
        if (threadIdx.x == 0) g_bn_cnt = 0;   // reset for next graph replay
    }
}

// ---------------- link scoring: bf16 gathers + fused BN+ReLU ----------------
__global__ void link_kernel(const int* __restrict__ eli, float* __restrict__ out)
{
    int w = (blockIdx.x * blockDim.x + threadIdx.x) >> 5;
    int lane = threadIdx.x & 31;
    if (w >= E_LABEL) return;
    int a = eli[w];
    int b = eli[E_LABEL + w];
    const int c0 = lane * 16;
    const uint4* pa = (const uint4*)&g_outb[a * HC + c0];
    const uint4* pb = (const uint4*)&g_outb[b * HC + c0];
    uint4 a0 = pa[0], a1 = pa[1];
    uint4 b0 = pb[0], b1 = pb[1];
    uint32_t ua[8] = {a0.x, a0.y, a0.z, a0.w, a1.x, a1.y, a1.z, a1.w};
    uint32_t ub[8] = {b0.x, b0.y, b0.z, b0.w, b1.x, b1.y, b1.z, b1.w};
    const float4* psc = (const float4*)&g_scale[c0];
    const float4* psh = (const float4*)&g_shift[c0];
    float sc[16], sh[16];
#pragma unroll
    for (int k = 0; k < 4; k++) {
        float4 c4 = psc[k], h4 = psh[k];
        sc[4*k+0] = c4.x; sc[4*k+1] = c4.y; sc[4*k+2] = c4.z; sc[4*k+3] = c4.w;
        sh[4*k+0] = h4.x; sh[4*k+1] = h4.y; sh[4*k+2] = h4.z; sh[4*k+3] = h4.w;
    }
    float p = 0.f;
#pragma unroll
    for (int j8 = 0; j8 < 8; j8++) {
        float va0 = bflo(ua[j8]), va1 = bfhi(ua[j8]);
        float vb0 = bflo(ub[j8]), vb1 = bfhi(ub[j8]);
        float ax = fmaxf(fmaf(va0, sc[2*j8+0], sh[2*j8+0]), 0.f);
        float ay = fmaxf(fmaf(va1, sc[2*j8+1], sh[2*j8+1]), 0.f);
        float bx = fmaxf(fmaf(vb0, sc[2*j8+0], sh[2*j8+0]), 0.f);
        float by = fmaxf(fmaf(vb1, sc[2*j8+1], sh[2*j8+1]), 0.f);
        p = fmaf(ax, bx, p);
        p = fmaf(ay, by, p);
    }
#pragma unroll
    for (int off = 16; off > 0; off >>= 1)
        p += __shfl_xor_sync(0xffffffffu, p, off);
    if (lane == 0) out[w] = p;
}

// ---------------- launch ----------------
extern "C" void kernel_launch(void* const* d_in, const int* in_sizes, int n_in,
                              void* d_out, int out_size)
{
    const float* x     = (const float*)d_in[0];
    const int*   ei    = (const int*)  d_in[1];
    const int*   eli   = (const int*)  d_in[2];
    const float* W_l   = (const float*)d_in[3];
    const float* W_r   = (const float*)d_in[4];
    const float* att   = (const float*)d_in[5];
    const float* bias  = (const float*)d_in[6];
    const float* gamma = (const float*)d_in[7];
    const float* beta  = (const float*)d_in[8];
    float* out = (float*)d_out;

    static bool s_init = false;
    if (!s_init) {
        cudaFuncSetAttribute(gemm_tc_kernel,
                             cudaFuncAttributeMaxDynamicSharedMemorySize, GSMEM_TOTAL);
        s_init = true;
    }

    // #1 fused conversions (also zeroes g_deg)
    conv_fused_kernel<<<CONVX_BLOCKS + CONVW_BLOCKS, 256>>>(x, W_l, W_r);

    // #2-#3 CSR build front half
    hist_kernel<<<(E_EDGES + 255) / 256, 256>>>(ei);
    scan_blocks_kernel<<<20, 1024>>>();

    // #4 HMMA split-bf16 GEMMs (profiled slot)
    {
        dim3 g(HC / 128, N_PAD / 128, 2);
        gemm_tc_kernel<<<g, 256, GSMEM_TOTAL>>>();
    }

    // #5-#6 CSR build back half
    scan_add_kernel<<<20, 1024>>>();
    scatter_kernel<<<(E_EDGES + 255) / 256, 256>>>(ei);

    // #7 attention + aggregation (+ BN partial sums)
    attn_kernel<<<ATTN_BLOCKS, 128>>>(att, bias);

    // #8 merged BN reduction
    bn_reduce_kernel<<<BN1_BLOCKS, HC>>>(gamma, beta);

    // #9 link scoring with fused BN + ReLU (bf16 gathers)
    link_kernel<<<(E_LABEL * 32) / 256, 256>>>(eli, out);
}